// round 1
// baseline (speedup 1.0000x reference)
#include <cuda_runtime.h>
#include <math.h>

#define B_DIM 8
#define L_DIM 2048
#define D_DIM 256

// ---------------- attention tiling ----------------
#define BM 64          // query rows per CTA
#define BN 32          // key rows per tile
#define QS 260         // Q smem row stride (floats)
#define KSTR 260       // K smem row stride
#define PSTR 36        // P smem row stride
#define ATH 128        // threads per attention CTA
#define ASMEM ((BM*QS + BN*KSTR + BM*PSTR) * 4)

// ---------------- fusion tiling ----------------
#define FTH 128
#define FBM 64
#define CSTR 68

// scratch (device globals: allocation-free)
__device__ float g_aug[(size_t)B_DIM * L_DIM * D_DIM];
__device__ float g_Wa[D_DIM * D_DIM];
__device__ float g_Wb[D_DIM * D_DIM];
__device__ float g_Wc[D_DIM * D_DIM];
__device__ float g_ga[D_DIM];
__device__ float g_gb[D_DIM];
__device__ float g_gc[D_DIM];

// Fold z = [c2, a, c2*a, c2-a] weight blocks:
//   z@W = c2@(W1+W4) + a@(W2-W4) + (c2*a)@W3
__global__ void prep_kernel(const float* __restrict__ Wf, const float* __restrict__ Wg)
{
    int i = blockIdx.x * blockDim.x + threadIdx.x;
    if (i < D_DIM * D_DIM) {
        int k = i >> 8, d = i & 255;
        float w4 = Wf[(size_t)(768 + k) * D_DIM + d];
        g_Wa[i] = Wf[(size_t)k * D_DIM + d] + w4;
        g_Wb[i] = Wf[(size_t)(256 + k) * D_DIM + d] - w4;
        g_Wc[i] = Wf[(size_t)(512 + k) * D_DIM + d];
    }
    if (i < D_DIM) {
        float v4 = Wg[768 + i];
        g_ga[i] = Wg[i] + v4;
        g_gb[i] = Wg[256 + i] - v4;
        g_gc[i] = Wg[512 + i];
    }
}

// Flash-attention: aug[b,i,:] = softmax_j(c2[b,i]·c1[b,j], mask diag & c_mask) @ c1
// Thread map (128 thr): tx = tid&7 (key cols / out cols), ty = tid>>3 (rows).
// Row fragment:  i = ty + 16*m   (m=0..3)  -> conflict-free strided LDS
// Col fragment:  j = tx + 8*n    (n=0..3)
// Out cols:      c = 4*tx + 32*n (n=0..7)  -> float4 stores/loads
__global__ __launch_bounds__(ATH, 2)
void attn_kernel(const float* __restrict__ c1, const float* __restrict__ c2,
                 const unsigned char* __restrict__ cmask)
{
    extern __shared__ float smem[];
    float* Qs = smem;                 // [BM][QS]
    float* Ks = smem + BM * QS;       // [BN][KSTR]
    float* Ps = Ks + BN * KSTR;       // [BM][PSTR]

    const int tid = threadIdx.x;
    const int tx = tid & 7;
    const int ty = tid >> 3;
    const int b  = blockIdx.y;
    const int q0 = blockIdx.x * BM;

    const float* c2b = c2 + ((size_t)b * L_DIM + q0) * D_DIM;
    const float* c1b = c1 + (size_t)b * L_DIM * D_DIM;
    const unsigned char* mb = cmask + (size_t)b * L_DIM;

    // load Q tile (once)
    for (int idx = tid * 4; idx < BM * D_DIM; idx += ATH * 4) {
        int r = idx >> 8, c = idx & 255;
        *(float4*)(Qs + r * QS + c) = *(const float4*)(c2b + r * D_DIM + c);
    }

    float4 O4[4][8];
    #pragma unroll
    for (int m = 0; m < 4; m++)
        #pragma unroll
        for (int n = 0; n < 8; n++) O4[m][n] = make_float4(0.f, 0.f, 0.f, 0.f);
    float mrow[4] = {-1e30f, -1e30f, -1e30f, -1e30f};
    float lrow[4] = {0.f, 0.f, 0.f, 0.f};

    int irow[4];
    #pragma unroll
    for (int m = 0; m < 4; m++) irow[m] = q0 + ty + 16 * m;

    for (int k0 = 0; k0 < L_DIM; k0 += BN) {
        __syncthreads();   // previous phase B done with Ks/Ps
        for (int idx = tid * 4; idx < BN * D_DIM; idx += ATH * 4) {
            int r = idx >> 8, c = idx & 255;
            *(float4*)(Ks + r * KSTR + c) =
                *(const float4*)(c1b + (size_t)(k0 + r) * D_DIM + c);
        }
        __syncthreads();

        // ---- phase A: S = Q K^T ----
        float s[4][4];
        #pragma unroll
        for (int m = 0; m < 4; m++)
            #pragma unroll
            for (int n = 0; n < 4; n++) s[m][n] = 0.f;

        for (int d = 0; d < D_DIM; d += 4) {
            float4 av[4], bv[4];
            #pragma unroll
            for (int m = 0; m < 4; m++)
                av[m] = *(const float4*)(Qs + (ty + 16 * m) * QS + d);
            #pragma unroll
            for (int n = 0; n < 4; n++)
                bv[n] = *(const float4*)(Ks + (tx + 8 * n) * KSTR + d);
            #pragma unroll
            for (int m = 0; m < 4; m++)
                #pragma unroll
                for (int n = 0; n < 4; n++) {
                    s[m][n] += av[m].x * bv[n].x;
                    s[m][n] += av[m].y * bv[n].y;
                    s[m][n] += av[m].z * bv[n].z;
                    s[m][n] += av[m].w * bv[n].w;
                }
        }

        // ---- masks: diagonal + padded keys ----
        #pragma unroll
        for (int n = 0; n < 4; n++) {
            int j = k0 + tx + 8 * n;
            bool masked = (mb[j] != 0);
            #pragma unroll
            for (int m = 0; m < 4; m++)
                if (masked || j == irow[m]) s[m][n] = -1e30f;
        }

        // ---- online softmax ----
        float corr[4];
        #pragma unroll
        for (int m = 0; m < 4; m++) {
            float t = fmaxf(fmaxf(s[m][0], s[m][1]), fmaxf(s[m][2], s[m][3]));
            t = fmaxf(t, __shfl_xor_sync(0xffffffffu, t, 1));
            t = fmaxf(t, __shfl_xor_sync(0xffffffffu, t, 2));
            t = fmaxf(t, __shfl_xor_sync(0xffffffffu, t, 4));
            float mn = fmaxf(mrow[m], t);
            corr[m] = __expf(mrow[m] - mn);
            mrow[m] = mn;
            lrow[m] *= corr[m];
        }
        #pragma unroll
        for (int m = 0; m < 4; m++) {
            #pragma unroll
            for (int n = 0; n < 4; n++) {
                float p = __expf(s[m][n] - mrow[m]);
                lrow[m] += p;
                Ps[(ty + 16 * m) * PSTR + tx + 8 * n] = p;
            }
            #pragma unroll
            for (int n = 0; n < 8; n++) {
                O4[m][n].x *= corr[m]; O4[m][n].y *= corr[m];
                O4[m][n].z *= corr[m]; O4[m][n].w *= corr[m];
            }
        }
        __syncthreads();

        // ---- phase B: O += P @ K ----
        #pragma unroll 2
        for (int j = 0; j < BN; j += 4) {
            float4 pa[4];
            #pragma unroll
            for (int m = 0; m < 4; m++)
                pa[m] = *(const float4*)(Ps + (ty + 16 * m) * PSTR + j);
            #pragma unroll
            for (int jj = 0; jj < 4; jj++) {
                float4 kv[8];
                #pragma unroll
                for (int n = 0; n < 8; n++)
                    kv[n] = *(const float4*)(Ks + (j + jj) * KSTR + 4 * tx + 32 * n);
                #pragma unroll
                for (int m = 0; m < 4; m++) {
                    float pm = (jj == 0) ? pa[m].x : (jj == 1) ? pa[m].y
                             : (jj == 2) ? pa[m].z : pa[m].w;
                    #pragma unroll
                    for (int n = 0; n < 8; n++) {
                        O4[m][n].x += pm * kv[n].x;
                        O4[m][n].y += pm * kv[n].y;
                        O4[m][n].z += pm * kv[n].z;
                        O4[m][n].w += pm * kv[n].w;
                    }
                }
            }
        }
    }

    // finalize: all-reduce l over the 8 tx lanes, normalize, store aug
    #pragma unroll
    for (int m = 0; m < 4; m++) {
        float l = lrow[m];
        l += __shfl_xor_sync(0xffffffffu, l, 1);
        l += __shfl_xor_sync(0xffffffffu, l, 2);
        l += __shfl_xor_sync(0xffffffffu, l, 4);
        float inv = 1.0f / l;
        float* dst = g_aug + ((size_t)b * L_DIM + irow[m]) * D_DIM;
        #pragma unroll
        for (int n = 0; n < 8; n++) {
            float4 v = O4[m][n];
            v.x *= inv; v.y *= inv; v.z *= inv; v.w *= inv;
            *(float4*)(dst + 4 * tx + 32 * n) = v;
        }
    }
}

// out = g*tanh(c2@Wa + a@Wb + (c2*a)@Wc + bf) + (1-g)*c2,  g = sigmoid(...)
__global__ __launch_bounds__(FTH)
void fusion_kernel(const float* __restrict__ c2, const float* __restrict__ bf,
                   const float* __restrict__ bg, float* __restrict__ out)
{
    __shared__ float Cs[FBM * CSTR];
    __shared__ float As[FBM * CSTR];

    const int tid = threadIdx.x;
    const int tx = tid & 7;
    const int ty = tid >> 3;
    const size_t row0 = (size_t)blockIdx.x * FBM;

    float4 facc[4][8];
    #pragma unroll
    for (int m = 0; m < 4; m++)
        #pragma unroll
        for (int n = 0; n < 8; n++) facc[m][n] = make_float4(0.f, 0.f, 0.f, 0.f);
    float gacc[4] = {0.f, 0.f, 0.f, 0.f};

    for (int kc = 0; kc < D_DIM; kc += 64) {
        __syncthreads();
        for (int idx = tid * 4; idx < FBM * 64; idx += FTH * 4) {
            int r = idx >> 6, c = idx & 63;
            *(float4*)(Cs + r * CSTR + c) =
                *(const float4*)(c2 + (row0 + r) * D_DIM + kc + c);
            *(float4*)(As + r * CSTR + c) =
                *(const float4*)(g_aug + (row0 + r) * D_DIM + kc + c);
        }
        __syncthreads();

        for (int k = 0; k < 64; k += 4) {
            const int kg = kc + k;
            float4 a1[4], a2[4], a3[4];
            #pragma unroll
            for (int m = 0; m < 4; m++) {
                a1[m] = *(const float4*)(Cs + (ty + 16 * m) * CSTR + k);
                a2[m] = *(const float4*)(As + (ty + 16 * m) * CSTR + k);
                a3[m] = make_float4(a1[m].x * a2[m].x, a1[m].y * a2[m].y,
                                    a1[m].z * a2[m].z, a1[m].w * a2[m].w);
            }
            float4 ga4 = *(const float4*)(g_ga + kg);
            float4 gb4 = *(const float4*)(g_gb + kg);
            float4 gc4 = *(const float4*)(g_gc + kg);
            #pragma unroll
            for (int m = 0; m < 4; m++) {
                gacc[m] += a1[m].x*ga4.x + a1[m].y*ga4.y + a1[m].z*ga4.z + a1[m].w*ga4.w
                         + a2[m].x*gb4.x + a2[m].y*gb4.y + a2[m].z*gb4.z + a2[m].w*gb4.w
                         + a3[m].x*gc4.x + a3[m].y*gc4.y + a3[m].z*gc4.z + a3[m].w*gc4.w;
            }
            #pragma unroll
            for (int kk = 0; kk < 4; kk++) {
                const float* wa = g_Wa + (size_t)(kg + kk) * D_DIM;
                const float* wb = g_Wb + (size_t)(kg + kk) * D_DIM;
                const float* wc = g_Wc + (size_t)(kg + kk) * D_DIM;
                #pragma unroll
                for (int n = 0; n < 8; n++) {
                    const int col = 4 * tx + 32 * n;
                    float4 wav = *(const float4*)(wa + col);
                    float4 wbv = *(const float4*)(wb + col);
                    float4 wcv = *(const float4*)(wc + col);
                    #pragma unroll
                    for (int m = 0; m < 4; m++) {
                        float x1 = kk==0?a1[m].x:kk==1?a1[m].y:kk==2?a1[m].z:a1[m].w;
                        float x2 = kk==0?a2[m].x:kk==1?a2[m].y:kk==2?a2[m].z:a2[m].w;
                        float x3 = kk==0?a3[m].x:kk==1?a3[m].y:kk==2?a3[m].z:a3[m].w;
                        facc[m][n].x += x1*wav.x + x2*wbv.x + x3*wcv.x;
                        facc[m][n].y += x1*wav.y + x2*wbv.y + x3*wcv.y;
                        facc[m][n].z += x1*wav.z + x2*wbv.z + x3*wcv.z;
                        facc[m][n].w += x1*wav.w + x2*wbv.w + x3*wcv.w;
                    }
                }
            }
        }
    }

    const float bgv = bg[0];
    #pragma unroll
    for (int m = 0; m < 4; m++) {
        const size_t row = row0 + ty + 16 * m;
        float g = 1.0f / (1.0f + __expf(-(gacc[m] + bgv)));
        const float* c2r = c2 + row * D_DIM;
        float* outr = out + row * D_DIM;
        #pragma unroll
        for (int n = 0; n < 8; n++) {
            int col = 4 * tx + 32 * n;
            float4 bfv = *(const float4*)(bf + col);
            float4 f = facc[m][n];
            f.x = tanhf(f.x + bfv.x);
            f.y = tanhf(f.y + bfv.y);
            f.z = tanhf(f.z + bfv.z);
            f.w = tanhf(f.w + bfv.w);
            float4 cv = *(const float4*)(c2r + col);
            float4 o;
            o.x = g * f.x + (1.f - g) * cv.x;
            o.y = g * f.y + (1.f - g) * cv.y;
            o.z = g * f.z + (1.f - g) * cv.z;
            o.w = g * f.w + (1.f - g) * cv.w;
            *(float4*)(outr + col) = o;
        }
    }
}

extern "C" void kernel_launch(void* const* d_in, const int* in_sizes, int n_in,
                              void* d_out, int out_size)
{
    (void)in_sizes; (void)n_in; (void)out_size;
    const float* c1         = (const float*)d_in[0];
    const float* c2         = (const float*)d_in[1];
    const unsigned char* cm = (const unsigned char*)d_in[2];
    const float* Wf         = (const float*)d_in[3];
    const float* bf         = (const float*)d_in[4];
    const float* Wg         = (const float*)d_in[5];
    const float* bg         = (const float*)d_in[6];
    float* out              = (float*)d_out;

    prep_kernel<<<256, 256>>>(Wf, Wg);

    cudaFuncSetAttribute(attn_kernel, cudaFuncAttributeMaxDynamicSharedMemorySize, ASMEM);
    attn_kernel<<<dim3(L_DIM / BM, B_DIM), ATH, ASMEM>>>(c1, c2, cm);

    fusion_kernel<<<(B_DIM * L_DIM) / FBM, FTH>>>(c2, bf, bg, out);
}

// round 4
// speedup vs baseline: 1.8951x; 1.8951x over previous
#include <cuda_runtime.h>
#include <cuda_bf16.h>
#include <cstdint>
#include <math.h>

#define B_DIM 8
#define L_DIM 2048
#define D_DIM 256

// attention tiling
#define BM 128
#define BN 64
#define NTILE (L_DIM / BN)   // 32
#define ATH 256
#define L2E 1.44269504f
#define NEG_C (-57.7078016f) // -40 * log2(e)

// smem byte offsets
#define SQH 0
#define SQL 65536
#define SKH 131072
#define SKL 163840
#define SMSK 196608
#define ATT_SMEM 196624

// fusion tiling
#define FTH 128
#define FBM 64
#define CSTR 68

// ---------------- device scratch ----------------
__device__ float g_aug[(size_t)B_DIM * L_DIM * D_DIM];
__device__ float g_Wa[D_DIM * D_DIM];
__device__ float g_Wb[D_DIM * D_DIM];
__device__ float g_Wc[D_DIM * D_DIM];
__device__ float g_ga[D_DIM];
__device__ float g_gb[D_DIM];
__device__ float g_gc[D_DIM];
__device__ __nv_bfloat16 g_c1h[(size_t)B_DIM * L_DIM * D_DIM];
__device__ __nv_bfloat16 g_c1l[(size_t)B_DIM * L_DIM * D_DIM];
__device__ __nv_bfloat16 g_c2h[(size_t)B_DIM * L_DIM * D_DIM];
__device__ __nv_bfloat16 g_c2l[(size_t)B_DIM * L_DIM * D_DIM];

// ---------------- helpers ----------------
__device__ __forceinline__ uint32_t smem_u32(const void* p) {
    uint32_t a;
    asm("{ .reg .u64 t; cvta.to.shared.u64 t, %1; cvt.u32.u64 %0, t; }" : "=r"(a) : "l"(p));
    return a;
}
__device__ __forceinline__ void ldsm4(uint32_t addr, uint32_t r[4]) {
    asm volatile("ldmatrix.sync.aligned.m8n8.x4.shared.b16 {%0,%1,%2,%3}, [%4];"
        : "=r"(r[0]), "=r"(r[1]), "=r"(r[2]), "=r"(r[3]) : "r"(addr));
}
__device__ __forceinline__ void ldsm4t(uint32_t addr, uint32_t r[4]) {
    asm volatile("ldmatrix.sync.aligned.m8n8.x4.trans.shared.b16 {%0,%1,%2,%3}, [%4];"
        : "=r"(r[0]), "=r"(r[1]), "=r"(r[2]), "=r"(r[3]) : "r"(addr));
}
__device__ __forceinline__ void mma16816(float d[4], const uint32_t a[4], const uint32_t b[2]) {
    asm volatile(
        "mma.sync.aligned.m16n8k16.row.col.f32.bf16.bf16.f32 "
        "{%0,%1,%2,%3}, {%4,%5,%6,%7}, {%8,%9}, {%0,%1,%2,%3};"
        : "+f"(d[0]), "+f"(d[1]), "+f"(d[2]), "+f"(d[3])
        : "r"(a[0]), "r"(a[1]), "r"(a[2]), "r"(a[3]), "r"(b[0]), "r"(b[1]));
}
__device__ __forceinline__ float fast_ex2(float x) {
    float r;
    asm("ex2.approx.f32 %0, %1;" : "=f"(r) : "f"(x));
    return r;
}
__device__ __forceinline__ uint32_t packbf(float hi, float lo) {
    uint32_t d;
    asm("cvt.rn.bf16x2.f32 %0, %1, %2;" : "=r"(d) : "f"(hi), "f"(lo));
    return d;
}

// ---------------- prep: fold fusion weights ----------------
__global__ void prep_kernel(const float* __restrict__ Wf, const float* __restrict__ Wg)
{
    int i = blockIdx.x * blockDim.x + threadIdx.x;
    if (i < D_DIM * D_DIM) {
        int k = i >> 8, d = i & 255;
        float w4 = Wf[(size_t)(768 + k) * D_DIM + d];
        g_Wa[i] = Wf[(size_t)k * D_DIM + d] + w4;
        g_Wb[i] = Wf[(size_t)(256 + k) * D_DIM + d] - w4;
        g_Wc[i] = Wf[(size_t)(512 + k) * D_DIM + d];
    }
    if (i < D_DIM) {
        float v4 = Wg[768 + i];
        g_ga[i] = Wg[i] + v4;
        g_gb[i] = Wg[256 + i] - v4;
        g_gc[i] = Wg[512 + i];
    }
}

// ---------------- convert c1, c2 -> bf16 hi/lo ----------------
#define NV4 (B_DIM * L_DIM * D_DIM / 4)
__global__ void convert_hl(const float* __restrict__ c1, const float* __restrict__ c2)
{
    int idx = blockIdx.x * blockDim.x + threadIdx.x;
    const float* src;
    __nv_bfloat162 *oh, *ol;
    int k = idx;
    if (idx < NV4) {
        src = c1; oh = (__nv_bfloat162*)g_c1h; ol = (__nv_bfloat162*)g_c1l;
    } else {
        k = idx - NV4;
        src = c2; oh = (__nv_bfloat162*)g_c2h; ol = (__nv_bfloat162*)g_c2l;
    }
    float4 v = ((const float4*)src)[k];
    __nv_bfloat16 h0 = __float2bfloat16(v.x), h1 = __float2bfloat16(v.y);
    __nv_bfloat16 h2 = __float2bfloat16(v.z), h3 = __float2bfloat16(v.w);
    oh[k * 2]     = __nv_bfloat162(h0, h1);
    oh[k * 2 + 1] = __nv_bfloat162(h2, h3);
    ol[k * 2]     = __nv_bfloat162(__float2bfloat16(v.x - __bfloat162float(h0)),
                                   __float2bfloat16(v.y - __bfloat162float(h1)));
    ol[k * 2 + 1] = __nv_bfloat162(__float2bfloat16(v.z - __bfloat162float(h2)),
                                   __float2bfloat16(v.w - __bfloat162float(h3)));
}

// ---------------- attention: mma.sync flash, static-offset softmax ----------------
__global__ __launch_bounds__(ATH)
void attn_mma(const unsigned char* __restrict__ cmask)
{
    extern __shared__ char sm[];
    const uint32_t sb = smem_u32(sm);
    const int tid = threadIdx.x;
    const int lane = tid & 31;
    const int w = tid >> 5;
    const int b = blockIdx.y;
    const int q0 = blockIdx.x * BM;

    const int g  = lane >> 2;       // fragment row group
    const int t4 = lane & 3;        // fragment col group
    const int swz = lane & 7;
    const int r1 = (lane & 7) + 8 * ((lane >> 3) & 1);
    const int r2 = (lane & 7) + 8 * ((lane >> 4) & 1);
    const int s1 = (lane >> 3) & 1;
    const int s2 = (lane >> 4) & 1;

    // ---- load Q tile (hi/lo) with xor swizzle ----
    {
        const __nv_bfloat16* baseh = g_c2h + ((size_t)b * L_DIM + q0) * D_DIM;
        const __nv_bfloat16* basel = g_c2l + ((size_t)b * L_DIM + q0) * D_DIM;
        #pragma unroll
        for (int it = 0; it < 32; it++) {
            int chunk = it * ATH + tid;          // 0..8191
            int buf = chunk >> 12;
            int rem = chunk & 4095;
            int row = rem >> 5, ch = rem & 31;
            const __nv_bfloat16* src = (buf ? basel : baseh) + (size_t)row * D_DIM + ch * 8;
            uint4 v = *(const uint4*)src;
            uint32_t off = (uint32_t)(row * 512 + ((ch ^ (row & 7)) << 4));
            *(uint4*)(sm + (buf ? SQL : SQH) + off) = v;
        }
    }

    // per-thread ldsm base addresses
    const uint32_t aQh = sb + SQH + (uint32_t)(16 * w + r1) * 512;
    const uint32_t aQl = sb + SQL + (uint32_t)(16 * w + r1) * 512;

    float O[32][4];
    #pragma unroll
    for (int n = 0; n < 32; n++)
        #pragma unroll
        for (int q = 0; q < 4; q++) O[n][q] = 0.f;
    float lac0 = 0.f, lac1 = 0.f;

    const unsigned char* mb = cmask + (size_t)b * L_DIM;
    const int rg = q0 + 16 * w + g;           // global row (first half)
    const int rowblk = (q0 + 16 * w) >> 6;
    const __nv_bfloat16* k1h = g_c1h + (size_t)b * L_DIM * D_DIM;
    const __nv_bfloat16* k1l = g_c1l + (size_t)b * L_DIM * D_DIM;

    for (int t = 0; t < NTILE; t++) {
        const int j0 = t * BN;
        __syncthreads();   // all warps done reading previous K tile
        #pragma unroll
        for (int it = 0; it < 16; it++) {
            int chunk = it * ATH + tid;          // 0..4095
            int buf = chunk >> 11;
            int rem = chunk & 2047;
            int row = rem >> 5, ch = rem & 31;
            const __nv_bfloat16* src = (buf ? k1l : k1h) + ((size_t)(j0 + row)) * D_DIM + ch * 8;
            uint4 v = *(const uint4*)src;
            uint32_t off = (uint32_t)(row * 512 + ((ch ^ (row & 7)) << 4));
            *(uint4*)(sm + (buf ? SKL : SKH) + off) = v;
        }
        if (tid < 64) {
            int mv = (mb[j0 + tid] != 0);
            unsigned bal = __ballot_sync(0xffffffffu, mv);
            if ((tid & 31) == 0) *(uint32_t*)(sm + SMSK + (tid >> 5) * 4) = bal;
        }
        __syncthreads();

        // ---- QK^T -> S (3-term bf16 split) ----
        float S[8][4];
        #pragma unroll
        for (int n = 0; n < 8; n++)
            #pragma unroll
            for (int q = 0; q < 4; q++) S[n][q] = 0.f;

        #pragma unroll
        for (int kt = 0; kt < 16; kt++) {
            uint32_t qh[4], ql[4];
            uint32_t aoff = (uint32_t)(((2 * kt + s2) ^ swz) << 4);
            ldsm4(aQh + aoff, qh);
            ldsm4(aQl + aoff, ql);
            #pragma unroll
            for (int np = 0; np < 4; np++) {
                uint32_t bh[4], bl[4];
                uint32_t badr = sb + (uint32_t)((16 * np + r2) * 512 + (((2 * kt + s1) ^ swz) << 4));
                ldsm4(badr + SKH, bh);
                ldsm4(badr + SKL, bl);
                mma16816(S[2 * np],     qh, bh);
                mma16816(S[2 * np],     qh, bl);
                mma16816(S[2 * np],     ql, bh);
                mma16816(S[2 * np + 1], qh, bh + 2);
                mma16816(S[2 * np + 1], qh, bl + 2);
                mma16816(S[2 * np + 1], ql, bh + 2);
            }
        }

        // ---- softmax: p = exp2(s*log2e - 40*log2e), mask diag + padded keys ----
        uint32_t mb0 = *(const uint32_t*)(sm + SMSK);
        uint32_t mb1 = *(const uint32_t*)(sm + SMSK + 4);
        uint64_t mbits = (uint64_t)mb0 | ((uint64_t)mb1 << 32);
        const bool dt = (rowblk == (j0 >> 6));
        const int dg = rg - j0, dg8 = dg + 8;

        uint32_t pg[8], pg8[8], qg[8], qg8[8];
        #pragma unroll
        for (int nt = 0; nt < 8; nt++) {
            int lc = 8 * nt + 2 * t4;
            float p0 = fast_ex2(S[nt][0] * L2E + NEG_C);
            float p1 = fast_ex2(S[nt][1] * L2E + NEG_C);
            float p2 = fast_ex2(S[nt][2] * L2E + NEG_C);
            float p3 = fast_ex2(S[nt][3] * L2E + NEG_C);
            if ((mbits >> lc) & 1)       { p0 = 0.f; p2 = 0.f; }
            if ((mbits >> (lc + 1)) & 1) { p1 = 0.f; p3 = 0.f; }
            if (dt) {
                if (lc == dg)      p0 = 0.f;
                if (lc + 1 == dg)  p1 = 0.f;
                if (lc == dg8)     p2 = 0.f;
                if (lc + 1 == dg8) p3 = 0.f;
            }
            lac0 += p0 + p1;
            lac1 += p2 + p3;
            uint32_t u0 = packbf(p1, p0);
            uint32_t u1 = packbf(p3, p2);
            pg[nt] = u0; pg8[nt] = u1;
            float h0 = __uint_as_float(u0 << 16);
            float h1 = __uint_as_float(u0 & 0xFFFF0000u);
            float h2 = __uint_as_float(u1 << 16);
            float h3 = __uint_as_float(u1 & 0xFFFF0000u);
            qg[nt]  = packbf(p1 - h1, p0 - h0);
            qg8[nt] = packbf(p3 - h3, p2 - h2);
        }

        // ---- O += P @ K (3-term bf16 split; B via ldmatrix.trans) ----
        #pragma unroll
        for (int kt = 0; kt < 4; kt++) {
            uint32_t ah[4] = {pg[2 * kt], pg8[2 * kt], pg[2 * kt + 1], pg8[2 * kt + 1]};
            uint32_t al[4] = {qg[2 * kt], qg8[2 * kt], qg[2 * kt + 1], qg8[2 * kt + 1]};
            #pragma unroll
            for (int np = 0; np < 16; np++) {
                uint32_t bh[4], bl[4];
                uint32_t badr = sb + (uint32_t)((16 * kt + r1) * 512 + (((2 * np + s2) ^ swz) << 4));
                ldsm4t(badr + SKH, bh);
                ldsm4t(badr + SKL, bl);
                mma16816(O[2 * np],     ah, bh);
                mma16816(O[2 * np],     ah, bl);
                mma16816(O[2 * np],     al, bh);
                mma16816(O[2 * np + 1], ah, bh + 2);
                mma16816(O[2 * np + 1], ah, bl + 2);
                mma16816(O[2 * np + 1], al, bh + 2);
            }
        }
    }

    // ---- finalize: reduce row sums over quad, normalize, store ----
    float l0 = lac0, l1 = lac1;
    l0 += __shfl_xor_sync(0xffffffffu, l0, 1);
    l0 += __shfl_xor_sync(0xffffffffu, l0, 2);
    l1 += __shfl_xor_sync(0xffffffffu, l1, 1);
    l1 += __shfl_xor_sync(0xffffffffu, l1, 2);
    float inv0 = 1.0f / l0, inv1 = 1.0f / l1;

    float* d0 = g_aug + ((size_t)b * L_DIM + rg) * D_DIM;
    float* d1 = d0 + 8 * D_DIM;
    #pragma unroll
    for (int nt = 0; nt < 32; nt++) {
        int col = 8 * nt + 2 * t4;
        *(float2*)(d0 + col) = make_float2(O[nt][0] * inv0, O[nt][1] * inv0);
        *(float2*)(d1 + col) = make_float2(O[nt][2] * inv1, O[nt][3] * inv1);
    }
}

// ---------------- fusion (FFMA) ----------------
__global__ __launch_bounds__(FTH)
void fusion_kernel(const float* __restrict__ c2, const float* __restrict__ bf,
                   const float* __restrict__ bg, float* __restrict__ out)
{
    __shared__ float Cs[FBM * CSTR];
    __shared__ float As[FBM * CSTR];

    const int tid = threadIdx.x;
    const int tx = tid & 7;
    const int ty = tid >> 3;
    const size_t row0 = (size_t)blockIdx.x * FBM;

    float4 facc[4][8];
    #pragma unroll
    for (int m = 0; m < 4; m++)
        #pragma unroll
        for (int n = 0; n < 8; n++) facc[m][n] = make_float4(0.f, 0.f, 0.f, 0.f);
    float gacc[4] = {0.f, 0.f, 0.f, 0.f};

    for (int kc = 0; kc < D_DIM; kc += 64) {
        __syncthreads();
        for (int idx = tid * 4; idx < FBM * 64; idx += FTH * 4) {
            int r = idx >> 6, c = idx & 63;
            *(float4*)(Cs + r * CSTR + c) =
                *(const float4*)(c2 + (row0 + r) * D_DIM + kc + c);
            *(float4*)(As + r * CSTR + c) =
                *(const float4*)(g_aug + (row0 + r) * D_DIM + kc + c);
        }
        __syncthreads();

        for (int k = 0; k < 64; k += 4) {
            const int kg = kc + k;
            float4 a1[4], a2[4], a3[4];
            #pragma unroll
            for (int m = 0; m < 4; m++) {
                a1[m] = *(const float4*)(Cs + (ty + 16 * m) * CSTR + k);
                a2[m] = *(const float4*)(As + (ty + 16 * m) * CSTR + k);
                a3[m] = make_float4(a1[m].x * a2[m].x, a1[m].y * a2[m].y,
                                    a1[m].z * a2[m].z, a1[m].w * a2[m].w);
            }
            float4 ga4 = *(const float4*)(g_ga + kg);
            float4 gb4 = *(const float4*)(g_gb + kg);
            float4 gc4 = *(const float4*)(g_gc + kg);
            #pragma unroll
            for (int m = 0; m < 4; m++) {
                gacc[m] += a1[m].x*ga4.x + a1[m].y*ga4.y + a1[m].z*ga4.z + a1[m].w*ga4.w
                         + a2[m].x*gb4.x + a2[m].y*gb4.y + a2[m].z*gb4.z + a2[m].w*gb4.w
                         + a3[m].x*gc4.x + a3[m].y*gc4.y + a3[m].z*gc4.z + a3[m].w*gc4.w;
            }
            #pragma unroll
            for (int kk = 0; kk < 4; kk++) {
                const float* wa = g_Wa + (size_t)(kg + kk) * D_DIM;
                const float* wb = g_Wb + (size_t)(kg + kk) * D_DIM;
                const float* wc = g_Wc + (size_t)(kg + kk) * D_DIM;
                #pragma unroll
                for (int n = 0; n < 8; n++) {
                    const int col = 4 * tx + 32 * n;
                    float4 wav = *(const float4*)(wa + col);
                    float4 wbv = *(const float4*)(wb + col);
                    float4 wcv = *(const float4*)(wc + col);
                    #pragma unroll
                    for (int m = 0; m < 4; m++) {
                        float x1 = kk==0?a1[m].x:kk==1?a1[m].y:kk==2?a1[m].z:a1[m].w;
                        float x2 = kk==0?a2[m].x:kk==1?a2[m].y:kk==2?a2[m].z:a2[m].w;
                        float x3 = kk==0?a3[m].x:kk==1?a3[m].y:kk==2?a3[m].z:a3[m].w;
                        facc[m][n].x += x1*wav.x + x2*wbv.x + x3*wcv.x;
                        facc[m][n].y += x1*wav.y + x2*wbv.y + x3*wcv.y;
                        facc[m][n].z += x1*wav.z + x2*wbv.z + x3*wcv.z;
                        facc[m][n].w += x1*wav.w + x2*wbv.w + x3*wcv.w;
                    }
                }
            }
        }
    }

    const float bgv = bg[0];
    #pragma unroll
    for (int m = 0; m < 4; m++) {
        const size_t row = row0 + ty + 16 * m;
        float gv = 1.0f / (1.0f + __expf(-(gacc[m] + bgv)));
        const float* c2r = c2 + row * D_DIM;
        float* outr = out + row * D_DIM;
        #pragma unroll
        for (int n = 0; n < 8; n++) {
            int col = 4 * tx + 32 * n;
            float4 bfv = *(const float4*)(bf + col);
            float4 f = facc[m][n];
            f.x = tanhf(f.x + bfv.x);
            f.y = tanhf(f.y + bfv.y);
            f.z = tanhf(f.z + bfv.z);
            f.w = tanhf(f.w + bfv.w);
            float4 cv = *(const float4*)(c2r + col);
            float4 o;
            o.x = gv * f.x + (1.f - gv) * cv.x;
            o.y = gv * f.y + (1.f - gv) * cv.y;
            o.z = gv * f.z + (1.f - gv) * cv.z;
            o.w = gv * f.w + (1.f - gv) * cv.w;
            *(float4*)(outr + col) = o;
        }
    }
}

extern "C" void kernel_launch(void* const* d_in, const int* in_sizes, int n_in,
                              void* d_out, int out_size)
{
    (void)in_sizes; (void)n_in; (void)out_size;
    const float* c1         = (const float*)d_in[0];
    const float* c2         = (const float*)d_in[1];
    const unsigned char* cm = (const unsigned char*)d_in[2];
    const float* Wf         = (const float*)d_in[3];
    const float* bf         = (const float*)d_in[4];
    const float* Wg         = (const float*)d_in[5];
    const float* bg         = (const float*)d_in[6];
    float* out              = (float*)d_out;

    prep_kernel<<<256, 256>>>(Wf, Wg);
    convert_hl<<<2 * NV4 / 256, 256>>>(c1, c2);

    cudaFuncSetAttribute(attn_mma, cudaFuncAttributeMaxDynamicSharedMemorySize, ATT_SMEM);
    attn_mma<<<dim3(L_DIM / BM, B_DIM), ATH, ATT_SMEM>>>(cm);

    fusion_kernel<<<(B_DIM * L_DIM) / FBM, FTH>>>(c2, bf, bg, out);
}

// round 6
// speedup vs baseline: 3.1952x; 1.6860x over previous
#include <cuda_runtime.h>
#include <cuda_bf16.h>
#include <cstdint>
#include <math.h>

#define B_DIM 8
#define L_DIM 2048
#define D_DIM 256
#define NROW (B_DIM * L_DIM)

// attention tiling
#define BM 128
#define BN 64
#define NTILE (L_DIM / BN)   // 32
#define ATH 256
#define L2E 1.44269504f
#define NEG_C (-57.7078016f) // -40 * log2(e)

// attention smem byte offsets
#define SQH 0
#define SQL 65536
#define SKH 131072
#define SKL 163840
#define SMSK 196608
#define SG   196624
#define ATT_SMEM 199808

// fusion smem byte offsets
#define FS_AH 0
#define FS_AL 16384
#define FS_WH 32768
#define FS_WL 65536
#define FS_BF 98304
#define FUS_SMEM 99328

// ---------------- device scratch ----------------
__device__ float g_ga[D_DIM];
__device__ float g_gb[D_DIM];
__device__ float g_gc[D_DIM];
__device__ float g_gate[NROW];
__device__ __nv_bfloat16 g_Wch[3 * D_DIM * D_DIM];   // [768][256] folded weights hi
__device__ __nv_bfloat16 g_Wcl[3 * D_DIM * D_DIM];   // lo
__device__ __nv_bfloat16 g_c1h[(size_t)NROW * D_DIM];
__device__ __nv_bfloat16 g_c1l[(size_t)NROW * D_DIM];
__device__ __nv_bfloat16 g_c2h[(size_t)NROW * D_DIM];
__device__ __nv_bfloat16 g_c2l[(size_t)NROW * D_DIM];
__device__ __nv_bfloat16 g_augh[(size_t)NROW * D_DIM];
__device__ __nv_bfloat16 g_augl[(size_t)NROW * D_DIM];
__device__ __nv_bfloat16 g_prodh[(size_t)NROW * D_DIM];
__device__ __nv_bfloat16 g_prodl[(size_t)NROW * D_DIM];

// ---------------- helpers ----------------
__device__ __forceinline__ uint32_t smem_u32(const void* p) {
    uint32_t a;
    asm("{ .reg .u64 t; cvta.to.shared.u64 t, %1; cvt.u32.u64 %0, t; }" : "=r"(a) : "l"(p));
    return a;
}
__device__ __forceinline__ void ldsm4(uint32_t addr, uint32_t r[4]) {
    asm volatile("ldmatrix.sync.aligned.m8n8.x4.shared.b16 {%0,%1,%2,%3}, [%4];"
        : "=r"(r[0]), "=r"(r[1]), "=r"(r[2]), "=r"(r[3]) : "r"(addr));
}
__device__ __forceinline__ void ldsm4t(uint32_t addr, uint32_t r[4]) {
    asm volatile("ldmatrix.sync.aligned.m8n8.x4.trans.shared.b16 {%0,%1,%2,%3}, [%4];"
        : "=r"(r[0]), "=r"(r[1]), "=r"(r[2]), "=r"(r[3]) : "r"(addr));
}
__device__ __forceinline__ void mma16816(float d[4], const uint32_t a[4], const uint32_t b[2]) {
    asm volatile(
        "mma.sync.aligned.m16n8k16.row.col.f32.bf16.bf16.f32 "
        "{%0,%1,%2,%3}, {%4,%5,%6,%7}, {%8,%9}, {%0,%1,%2,%3};"
        : "+f"(d[0]), "+f"(d[1]), "+f"(d[2]), "+f"(d[3])
        : "r"(a[0]), "r"(a[1]), "r"(a[2]), "r"(a[3]), "r"(b[0]), "r"(b[1]));
}
__device__ __forceinline__ float fast_ex2(float x) {
    float r;
    asm("ex2.approx.f32 %0, %1;" : "=f"(r) : "f"(x));
    return r;
}
__device__ __forceinline__ uint32_t packbf(float hi, float lo) {
    uint32_t d;
    asm("cvt.rn.bf16x2.f32 %0, %1, %2;" : "=r"(d) : "f"(hi), "f"(lo));
    return d;
}

// ---------------- prep: fold fusion weights, split to bf16 ----------------
__global__ void prep_kernel(const float* __restrict__ Wf, const float* __restrict__ Wg)
{
    int i = blockIdx.x * blockDim.x + threadIdx.x;
    if (i < D_DIM * D_DIM) {
        int k = i >> 8, d = i & 255;
        float w4 = Wf[(size_t)(768 + k) * D_DIM + d];
        float wa = Wf[(size_t)k * D_DIM + d] + w4;
        float wb = Wf[(size_t)(256 + k) * D_DIM + d] - w4;
        float wc = Wf[(size_t)(512 + k) * D_DIM + d];
        float w3[3] = {wa, wb, wc};
        #pragma unroll
        for (int tmc = 0; tmc < 3; tmc++) {
            __nv_bfloat16 h = __float2bfloat16(w3[tmc]);
            size_t o = (size_t)(tmc * D_DIM + k) * D_DIM + d;
            g_Wch[o] = h;
            g_Wcl[o] = __float2bfloat16(w3[tmc] - __bfloat162float(h));
        }
    }
    if (i < D_DIM) {
        float v4 = Wg[768 + i];
        g_ga[i] = Wg[i] + v4;
        g_gb[i] = Wg[256 + i] - v4;
        g_gc[i] = Wg[512 + i];
    }
}

// ---------------- convert c1, c2 -> bf16 hi/lo ----------------
#define NV4 (NROW * D_DIM / 4)
__global__ void convert_hl(const float* __restrict__ c1, const float* __restrict__ c2)
{
    int idx = blockIdx.x * blockDim.x + threadIdx.x;
    const float* src;
    __nv_bfloat162 *oh, *ol;
    int k = idx;
    if (idx < NV4) {
        src = c1; oh = (__nv_bfloat162*)g_c1h; ol = (__nv_bfloat162*)g_c1l;
    } else {
        k = idx - NV4;
        src = c2; oh = (__nv_bfloat162*)g_c2h; ol = (__nv_bfloat162*)g_c2l;
    }
    float4 v = ((const float4*)src)[k];
    __nv_bfloat16 h0 = __float2bfloat16(v.x), h1 = __float2bfloat16(v.y);
    __nv_bfloat16 h2 = __float2bfloat16(v.z), h3 = __float2bfloat16(v.w);
    oh[k * 2]     = __nv_bfloat162(h0, h1);
    oh[k * 2 + 1] = __nv_bfloat162(h2, h3);
    ol[k * 2]     = __nv_bfloat162(__float2bfloat16(v.x - __bfloat162float(h0)),
                                   __float2bfloat16(v.y - __bfloat162float(h1)));
    ol[k * 2 + 1] = __nv_bfloat162(__float2bfloat16(v.z - __bfloat162float(h2)),
                                   __float2bfloat16(v.w - __bfloat162float(h3)));
}

// ---------------- attention: mma.sync flash, static-offset softmax ----------------
// Epilogue also emits aug/prod bf16 hi/lo + fp32 gate dot-products.
__global__ __launch_bounds__(ATH)
void attn_mma(const unsigned char* __restrict__ cmask, const float* __restrict__ c2)
{
    extern __shared__ char sm[];
    const uint32_t sb = smem_u32(sm);
    const int tid = threadIdx.x;
    const int lane = tid & 31;
    const int w = tid >> 5;
    const int b = blockIdx.y;
    const int q0 = blockIdx.x * BM;

    const int g  = lane >> 2;
    const int t4 = lane & 3;
    const int swz = lane & 7;
    const int r1 = (lane & 7) + 8 * ((lane >> 3) & 1);
    const int r2 = (lane & 7) + 8 * ((lane >> 4) & 1);
    const int s1 = (lane >> 3) & 1;
    const int s2 = (lane >> 4) & 1;

    // stage gate vectors (ga/gb/gc) into smem
    {
        float* gs = (float*)(sm + SG);
        for (int i = tid; i < 256; i += ATH) {
            gs[i] = g_ga[i];
            gs[256 + i] = g_gb[i];
            gs[512 + i] = g_gc[i];
        }
    }

    // ---- load Q tile (hi/lo) with xor swizzle ----
    {
        const __nv_bfloat16* baseh = g_c2h + ((size_t)b * L_DIM + q0) * D_DIM;
        const __nv_bfloat16* basel = g_c2l + ((size_t)b * L_DIM + q0) * D_DIM;
        #pragma unroll
        for (int it = 0; it < 32; it++) {
            int chunk = it * ATH + tid;
            int buf = chunk >> 12;
            int rem = chunk & 4095;
            int row = rem >> 5, ch = rem & 31;
            const __nv_bfloat16* src = (buf ? basel : baseh) + (size_t)row * D_DIM + ch * 8;
            uint4 v = *(const uint4*)src;
            uint32_t off = (uint32_t)(row * 512 + ((ch ^ (row & 7)) << 4));
            *(uint4*)(sm + (buf ? SQL : SQH) + off) = v;
        }
    }

    const uint32_t aQh = sb + SQH + (uint32_t)(16 * w + r1) * 512;
    const uint32_t aQl = sb + SQL + (uint32_t)(16 * w + r1) * 512;

    float O[32][4];
    #pragma unroll
    for (int n = 0; n < 32; n++)
        #pragma unroll
        for (int q = 0; q < 4; q++) O[n][q] = 0.f;
    float lac0 = 0.f, lac1 = 0.f;

    const unsigned char* mb = cmask + (size_t)b * L_DIM;
    const int rg = q0 + 16 * w + g;
    const int rowblk = (q0 + 16 * w) >> 6;
    const __nv_bfloat16* k1h = g_c1h + (size_t)b * L_DIM * D_DIM;
    const __nv_bfloat16* k1l = g_c1l + (size_t)b * L_DIM * D_DIM;

    for (int t = 0; t < NTILE; t++) {
        const int j0 = t * BN;
        __syncthreads();
        #pragma unroll
        for (int it = 0; it < 16; it++) {
            int chunk = it * ATH + tid;
            int buf = chunk >> 11;
            int rem = chunk & 2047;
            int row = rem >> 5, ch = rem & 31;
            const __nv_bfloat16* src = (buf ? k1l : k1h) + ((size_t)(j0 + row)) * D_DIM + ch * 8;
            uint4 v = *(const uint4*)src;
            uint32_t off = (uint32_t)(row * 512 + ((ch ^ (row & 7)) << 4));
            *(uint4*)(sm + (buf ? SKL : SKH) + off) = v;
        }
        if (tid < 64) {
            int mv = (mb[j0 + tid] != 0);
            unsigned bal = __ballot_sync(0xffffffffu, mv);
            if ((tid & 31) == 0) *(uint32_t*)(sm + SMSK + (tid >> 5) * 4) = bal;
        }
        __syncthreads();

        // ---- QK^T -> S (3-term bf16 split) ----
        float S[8][4];
        #pragma unroll
        for (int n = 0; n < 8; n++)
            #pragma unroll
            for (int q = 0; q < 4; q++) S[n][q] = 0.f;

        #pragma unroll
        for (int kt = 0; kt < 16; kt++) {
            uint32_t qh[4], ql[4];
            uint32_t aoff = (uint32_t)(((2 * kt + s2) ^ swz) << 4);
            ldsm4(aQh + aoff, qh);
            ldsm4(aQl + aoff, ql);
            #pragma unroll
            for (int np = 0; np < 4; np++) {
                uint32_t bh[4], bl[4];
                uint32_t badr = sb + (uint32_t)((16 * np + r2) * 512 + (((2 * kt + s1) ^ swz) << 4));
                ldsm4(badr + SKH, bh);
                ldsm4(badr + SKL, bl);
                mma16816(S[2 * np],     qh, bh);
                mma16816(S[2 * np],     qh, bl);
                mma16816(S[2 * np],     ql, bh);
                mma16816(S[2 * np + 1], qh, bh + 2);
                mma16816(S[2 * np + 1], qh, bl + 2);
                mma16816(S[2 * np + 1], ql, bh + 2);
            }
        }

        // ---- softmax: p = exp2(s*log2e - 40*log2e), mask diag + padded keys ----
        uint32_t mb0 = *(const uint32_t*)(sm + SMSK);
        uint32_t mb1 = *(const uint32_t*)(sm + SMSK + 4);
        uint64_t mbits = (uint64_t)mb0 | ((uint64_t)mb1 << 32);
        const bool dt = (rowblk == (j0 >> 6));
        const int dg = rg - j0, dg8 = dg + 8;

        uint32_t pg[8], pg8[8], qg[8], qg8[8];
        #pragma unroll
        for (int nt = 0; nt < 8; nt++) {
            int lc = 8 * nt + 2 * t4;
            float p0 = fast_ex2(S[nt][0] * L2E + NEG_C);
            float p1 = fast_ex2(S[nt][1] * L2E + NEG_C);
            float p2 = fast_ex2(S[nt][2] * L2E + NEG_C);
            float p3 = fast_ex2(S[nt][3] * L2E + NEG_C);
            if ((mbits >> lc) & 1)       { p0 = 0.f; p2 = 0.f; }
            if ((mbits >> (lc + 1)) & 1) { p1 = 0.f; p3 = 0.f; }
            if (dt) {
                if (lc == dg)      p0 = 0.f;
                if (lc + 1 == dg)  p1 = 0.f;
                if (lc == dg8)     p2 = 0.f;
                if (lc + 1 == dg8) p3 = 0.f;
            }
            lac0 += p0 + p1;
            lac1 += p2 + p3;
            uint32_t u0 = packbf(p1, p0);
            uint32_t u1 = packbf(p3, p2);
            pg[nt] = u0; pg8[nt] = u1;
            float h0 = __uint_as_float(u0 << 16);
            float h1 = __uint_as_float(u0 & 0xFFFF0000u);
            float h2 = __uint_as_float(u1 << 16);
            float h3 = __uint_as_float(u1 & 0xFFFF0000u);
            qg[nt]  = packbf(p1 - h1, p0 - h0);
            qg8[nt] = packbf(p3 - h3, p2 - h2);
        }

        // ---- O += P @ K (3-term bf16 split; B via ldmatrix.trans) ----
        #pragma unroll
        for (int kt = 0; kt < 4; kt++) {
            uint32_t ah[4] = {pg[2 * kt], pg8[2 * kt], pg[2 * kt + 1], pg8[2 * kt + 1]};
            uint32_t al[4] = {qg[2 * kt], qg8[2 * kt], qg[2 * kt + 1], qg8[2 * kt + 1]};
            #pragma unroll
            for (int np = 0; np < 16; np++) {
                uint32_t bh[4], bl[4];
                uint32_t badr = sb + (uint32_t)((16 * kt + r1) * 512 + (((2 * np + s2) ^ swz) << 4));
                ldsm4t(badr + SKH, bh);
                ldsm4t(badr + SKL, bl);
                mma16816(O[2 * np],     ah, bh);
                mma16816(O[2 * np],     ah, bl);
                mma16816(O[2 * np],     al, bh);
                mma16816(O[2 * np + 1], ah, bh + 2);
                mma16816(O[2 * np + 1], ah, bl + 2);
                mma16816(O[2 * np + 1], al, bh + 2);
            }
        }
    }

    // ---- finalize: normalize, compute prod + gate, emit bf16 splits ----
    float l0 = lac0, l1 = lac1;
    l0 += __shfl_xor_sync(0xffffffffu, l0, 1);
    l0 += __shfl_xor_sync(0xffffffffu, l0, 2);
    l1 += __shfl_xor_sync(0xffffffffu, l1, 1);
    l1 += __shfl_xor_sync(0xffffffffu, l1, 2);
    float inv0 = 1.0f / l0, inv1 = 1.0f / l1;

    const size_t r0e = ((size_t)b * L_DIM + rg) * D_DIM;
    const size_t r1e = r0e + 8 * D_DIM;
    const float* c2r0 = c2 + r0e;
    const float* c2r1 = c2 + r1e;
    uint32_t* augh32 = (uint32_t*)g_augh;
    uint32_t* augl32 = (uint32_t*)g_augl;
    uint32_t* prodh32 = (uint32_t*)g_prodh;
    uint32_t* prodl32 = (uint32_t*)g_prodl;
    const float* gs = (const float*)(sm + SG);
    float gate0 = 0.f, gate1 = 0.f;

    #pragma unroll
    for (int nt = 0; nt < 32; nt++) {
        int col = 8 * nt + 2 * t4;
        float a0 = O[nt][0] * inv0, a1 = O[nt][1] * inv0;
        float b0 = O[nt][2] * inv1, b1 = O[nt][3] * inv1;
        float2 x0 = *(const float2*)(c2r0 + col);
        float2 x1 = *(const float2*)(c2r1 + col);
        float p0 = x0.x * a0, p1 = x0.y * a1;
        float p2 = x1.x * b0, p3 = x1.y * b1;
        float ga0 = gs[col], ga1 = gs[col + 1];
        float gb0 = gs[256 + col], gb1 = gs[257 + col];
        float gc0 = gs[512 + col], gc1 = gs[513 + col];
        gate0 += x0.x * ga0 + x0.y * ga1 + a0 * gb0 + a1 * gb1 + p0 * gc0 + p1 * gc1;
        gate1 += x1.x * ga0 + x1.y * ga1 + b0 * gb0 + b1 * gb1 + p2 * gc0 + p3 * gc1;

        uint32_t ah = packbf(a1, a0);
        float ah0 = __uint_as_float(ah << 16), ah1 = __uint_as_float(ah & 0xFFFF0000u);
        uint32_t alw = packbf(a1 - ah1, a0 - ah0);
        uint32_t bh = packbf(b1, b0);
        float bh0 = __uint_as_float(bh << 16), bh1 = __uint_as_float(bh & 0xFFFF0000u);
        uint32_t blw = packbf(b1 - bh1, b0 - bh0);
        uint32_t ph = packbf(p1, p0);
        float ph0 = __uint_as_float(ph << 16), ph1 = __uint_as_float(ph & 0xFFFF0000u);
        uint32_t plw = packbf(p1 - ph1, p0 - ph0);
        uint32_t ph2 = packbf(p3, p2);
        float pc0 = __uint_as_float(ph2 << 16), pc1 = __uint_as_float(ph2 & 0xFFFF0000u);
        uint32_t plw2 = packbf(p3 - pc1, p2 - pc0);

        size_t i0 = (r0e + col) >> 1, i1 = (r1e + col) >> 1;
        augh32[i0] = ah;   augl32[i0] = alw;
        augh32[i1] = bh;   augl32[i1] = blw;
        prodh32[i0] = ph;  prodl32[i0] = plw;
        prodh32[i1] = ph2; prodl32[i1] = plw2;
    }

    gate0 += __shfl_xor_sync(0xffffffffu, gate0, 1);
    gate0 += __shfl_xor_sync(0xffffffffu, gate0, 2);
    gate1 += __shfl_xor_sync(0xffffffffu, gate1, 1);
    gate1 += __shfl_xor_sync(0xffffffffu, gate1, 2);
    if (t4 == 0) {
        g_gate[(size_t)b * L_DIM + rg] = gate0;
        g_gate[(size_t)b * L_DIM + rg + 8] = gate1;
    }
}

// ---------------- fusion on tensor cores ----------------
// out = g*tanh([c2|aug|prod] @ Wcat + bf) + (1-g)*c2,  g = sigmoid(gate + bg)
__global__ __launch_bounds__(256)
void fusion_tc(const float* __restrict__ c2, const float* __restrict__ bf,
               const float* __restrict__ bg, float* __restrict__ out)
{
    extern __shared__ char sm[];
    const uint32_t sb = smem_u32(sm);
    const int tid = threadIdx.x;
    const int lane = tid & 31;
    const int w = tid >> 5;
    const int g = lane >> 2;
    const int t4 = lane & 3;
    const int swz = lane & 7;
    const int r1 = (lane & 7) + 8 * ((lane >> 3) & 1);
    const int s2 = (lane >> 4) & 1;
    const size_t row0 = (size_t)blockIdx.x * 128;

    ((float*)(sm + FS_BF))[tid] = bf[tid];   // 256 threads, 256 cols

    float O[32][4];
    #pragma unroll
    for (int n = 0; n < 32; n++)
        #pragma unroll
        for (int q = 0; q < 4; q++) O[n][q] = 0.f;

    const __nv_bfloat16* srcsH[3] = {g_c2h + row0 * D_DIM, g_augh + row0 * D_DIM, g_prodh + row0 * D_DIM};
    const __nv_bfloat16* srcsL[3] = {g_c2l + row0 * D_DIM, g_augl + row0 * D_DIM, g_prodl + row0 * D_DIM};

    for (int kc = 0; kc < 12; kc++) {
        const int term = kc >> 2;
        const int koff = (kc & 3) * 64;
        __syncthreads();
        // A chunk [128 x 64] hi/lo: 1024 chunks per buffer, 2048 total
        #pragma unroll
        for (int it = 0; it < 8; it++) {
            int chunk = it * 256 + tid;
            int buf = chunk >> 10, rem = chunk & 1023;
            int row = rem >> 3, ch = rem & 7;
            const __nv_bfloat16* src = (buf ? srcsL[term] : srcsH[term]) + (size_t)row * D_DIM + koff + ch * 8;
            uint4 v = *(const uint4*)src;
            *(uint4*)(sm + (buf ? FS_AL : FS_AH) + row * 128 + ((ch ^ (row & 7)) << 4)) = v;
        }
        // W chunk [64 x 256] hi/lo: 2048 chunks per buffer, 4096 total
        const int krow0 = term * 256 + koff;
        #pragma unroll
        for (int it = 0; it < 16; it++) {
            int chunk = it * 256 + tid;
            int buf = chunk >> 11, rem = chunk & 2047;
            int row = rem >> 5, ch = rem & 31;
            const __nv_bfloat16* src = (buf ? g_Wcl : g_Wch) + (size_t)(krow0 + row) * D_DIM + ch * 8;
            uint4 v = *(const uint4*)src;
            *(uint4*)(sm + (buf ? FS_WL : FS_WH) + row * 512 + ((ch ^ (row & 7)) << 4)) = v;
        }
        __syncthreads();

        const uint32_t aAh = sb + FS_AH + (uint32_t)(16 * w + r1) * 128;
        const uint32_t aAl = sb + FS_AL + (uint32_t)(16 * w + r1) * 128;
        #pragma unroll
        for (int kt = 0; kt < 4; kt++) {
            uint32_t ah[4], al[4];
            uint32_t aoff = (uint32_t)(((2 * kt + s2) ^ swz) << 4);
            ldsm4(aAh + aoff, ah);
            ldsm4(aAl + aoff, al);
            #pragma unroll
            for (int np = 0; np < 16; np++) {
                uint32_t bh[4], bl[4];
                uint32_t badr = sb + (uint32_t)((16 * kt + r1) * 512 + (((2 * np + s2) ^ swz) << 4));
                ldsm4t(badr + FS_WH, bh);
                ldsm4t(badr + FS_WL, bl);
                mma16816(O[2 * np],     ah, bh);
                mma16816(O[2 * np],     ah, bl);
                mma16816(O[2 * np],     al, bh);
                mma16816(O[2 * np + 1], ah, bh + 2);
                mma16816(O[2 * np + 1], ah, bl + 2);
                mma16816(O[2 * np + 1], al, bh + 2);
            }
        }
    }

    // epilogue
    const size_t rg = row0 + 16 * w + g;
    const float bgv = bg[0];
    float gv0 = 1.0f / (1.0f + __expf(-(g_gate[rg] + bgv)));
    float gv1 = 1.0f / (1.0f + __expf(-(g_gate[rg + 8] + bgv)));
    const float* c2r0 = c2 + rg * D_DIM;
    const float* c2r1 = c2r0 + 8 * D_DIM;
    float* o0 = out + rg * D_DIM;
    float* o1 = o0 + 8 * D_DIM;
    const float* bfs = (const float*)(sm + FS_BF);

    #pragma unroll
    for (int nt = 0; nt < 32; nt++) {
        int col = 8 * nt + 2 * t4;
        float2 bv = *(const float2*)(bfs + col);
        float2 x0 = *(const float2*)(c2r0 + col);
        float2 x1 = *(const float2*)(c2r1 + col);
        float f0 = tanhf(O[nt][0] + bv.x);
        float f1 = tanhf(O[nt][1] + bv.y);
        float f2 = tanhf(O[nt][2] + bv.x);
        float f3 = tanhf(O[nt][3] + bv.y);
        *(float2*)(o0 + col) = make_float2(gv0 * f0 + (1.f - gv0) * x0.x,
                                           gv0 * f1 + (1.f - gv0) * x0.y);
        *(float2*)(o1 + col) = make_float2(gv1 * f2 + (1.f - gv1) * x1.x,
                                           gv1 * f3 + (1.f - gv1) * x1.y);
    }
}

extern "C" void kernel_launch(void* const* d_in, const int* in_sizes, int n_in,
                              void* d_out, int out_size)
{
    (void)in_sizes; (void)n_in; (void)out_size;
    const float* c1         = (const float*)d_in[0];
    const float* c2         = (const float*)d_in[1];
    const unsigned char* cm = (const unsigned char*)d_in[2];
    const float* Wf         = (const float*)d_in[3];
    const float* bf         = (const float*)d_in[4];
    const float* Wg         = (const float*)d_in[5];
    const float* bg         = (const float*)d_in[6];
    float* out              = (float*)d_out;

    prep_kernel<<<256, 256>>>(Wf, Wg);
    convert_hl<<<2 * NV4 / 256, 256>>>(c1, c2);

    cudaFuncSetAttribute(attn_mma, cudaFuncAttributeMaxDynamicSharedMemorySize, ATT_SMEM);
    attn_mma<<<dim3(L_DIM / BM, B_DIM), ATH, ATT_SMEM>>>(cm, c2);

    cudaFuncSetAttribute(fusion_tc, cudaFuncAttributeMaxDynamicSharedMemorySize, FUS_SMEM);
    fusion_tc<<<NROW / 128, 256, FUS_SMEM>>>(c2, bf, bg, out);
}

// round 7
// speedup vs baseline: 3.5405x; 1.1081x over previous
#include <cuda_runtime.h>
#include <cuda_bf16.h>
#include <cstdint>
#include <math.h>

#define B_DIM 8
#define L_DIM 2048
#define D_DIM 256
#define NROW (B_DIM * L_DIM)

// attention tiling
#define BM 128
#define BN 64
#define NTILE (L_DIM / BN)   // 32
#define ATH 256
#define L2E 1.44269504f
#define NEG_C (-57.7078016f) // -40 * log2(e)

// attention smem byte offsets
#define SQH 0
#define SQL 65536
#define SKH 131072
#define SKL 163840
#define SMSK 196608
#define SG   196624
#define ATT_SMEM 199808

// fusion smem: two 96KB stages + bf
#define FSTG 98304
#define FS_BF 196608
#define FUS_SMEM 197632

// ---------------- device scratch ----------------
__device__ float g_ga[D_DIM];
__device__ float g_gb[D_DIM];
__device__ float g_gc[D_DIM];
__device__ float g_gate[NROW];
__device__ __nv_bfloat16 g_Wch[3 * D_DIM * D_DIM];   // [768][256] folded weights hi
__device__ __nv_bfloat16 g_Wcl[3 * D_DIM * D_DIM];   // lo
__device__ __nv_bfloat16 g_c1h[(size_t)NROW * D_DIM];
__device__ __nv_bfloat16 g_c1l[(size_t)NROW * D_DIM];
__device__ __nv_bfloat16 g_c2h[(size_t)NROW * D_DIM];
__device__ __nv_bfloat16 g_c2l[(size_t)NROW * D_DIM];
__device__ __nv_bfloat16 g_augh[(size_t)NROW * D_DIM];
__device__ __nv_bfloat16 g_augl[(size_t)NROW * D_DIM];
__device__ __nv_bfloat16 g_prodh[(size_t)NROW * D_DIM];
__device__ __nv_bfloat16 g_prodl[(size_t)NROW * D_DIM];

// ---------------- helpers ----------------
__device__ __forceinline__ uint32_t smem_u32(const void* p) {
    uint32_t a;
    asm("{ .reg .u64 t; cvta.to.shared.u64 t, %1; cvt.u32.u64 %0, t; }" : "=r"(a) : "l"(p));
    return a;
}
#define CP16(dst, src) asm volatile("cp.async.cg.shared.global [%0], [%1], 16;" :: "r"(dst), "l"(src))
#define CP_COMMIT()    asm volatile("cp.async.commit_group;" ::: "memory")
#define CP_WAIT(n)     asm volatile("cp.async.wait_group %0;" :: "n"(n) : "memory")

__device__ __forceinline__ void ldsm4(uint32_t addr, uint32_t r[4]) {
    asm volatile("ldmatrix.sync.aligned.m8n8.x4.shared.b16 {%0,%1,%2,%3}, [%4];"
        : "=r"(r[0]), "=r"(r[1]), "=r"(r[2]), "=r"(r[3]) : "r"(addr));
}
__device__ __forceinline__ void ldsm4t(uint32_t addr, uint32_t r[4]) {
    asm volatile("ldmatrix.sync.aligned.m8n8.x4.trans.shared.b16 {%0,%1,%2,%3}, [%4];"
        : "=r"(r[0]), "=r"(r[1]), "=r"(r[2]), "=r"(r[3]) : "r"(addr));
}
__device__ __forceinline__ void mma16816(float d[4], const uint32_t a[4], const uint32_t b[2]) {
    asm volatile(
        "mma.sync.aligned.m16n8k16.row.col.f32.bf16.bf16.f32 "
        "{%0,%1,%2,%3}, {%4,%5,%6,%7}, {%8,%9}, {%0,%1,%2,%3};"
        : "+f"(d[0]), "+f"(d[1]), "+f"(d[2]), "+f"(d[3])
        : "r"(a[0]), "r"(a[1]), "r"(a[2]), "r"(a[3]), "r"(b[0]), "r"(b[1]));
}
__device__ __forceinline__ float fast_ex2(float x) {
    float r;
    asm("ex2.approx.f32 %0, %1;" : "=f"(r) : "f"(x));
    return r;
}
__device__ __forceinline__ uint32_t packbf(float hi, float lo) {
    uint32_t d;
    asm("cvt.rn.bf16x2.f32 %0, %1, %2;" : "=r"(d) : "f"(hi), "f"(lo));
    return d;
}

// ---------------- prep: fold fusion weights, split to bf16 ----------------
__global__ void prep_kernel(const float* __restrict__ Wf, const float* __restrict__ Wg)
{
    int i = blockIdx.x * blockDim.x + threadIdx.x;
    if (i < D_DIM * D_DIM) {
        int k = i >> 8, d = i & 255;
        float w4 = Wf[(size_t)(768 + k) * D_DIM + d];
        float wa = Wf[(size_t)k * D_DIM + d] + w4;
        float wb = Wf[(size_t)(256 + k) * D_DIM + d] - w4;
        float wc = Wf[(size_t)(512 + k) * D_DIM + d];
        float w3[3] = {wa, wb, wc};
        #pragma unroll
        for (int tmc = 0; tmc < 3; tmc++) {
            __nv_bfloat16 h = __float2bfloat16(w3[tmc]);
            size_t o = (size_t)(tmc * D_DIM + k) * D_DIM + d;
            g_Wch[o] = h;
            g_Wcl[o] = __float2bfloat16(w3[tmc] - __bfloat162float(h));
        }
    }
    if (i < D_DIM) {
        float v4 = Wg[768 + i];
        g_ga[i] = Wg[i] + v4;
        g_gb[i] = Wg[256 + i] - v4;
        g_gc[i] = Wg[512 + i];
    }
}

// ---------------- convert c1, c2 -> bf16 hi/lo ----------------
#define NV4 (NROW * D_DIM / 4)
__global__ void convert_hl(const float* __restrict__ c1, const float* __restrict__ c2)
{
    int idx = blockIdx.x * blockDim.x + threadIdx.x;
    const float* src;
    __nv_bfloat162 *oh, *ol;
    int k = idx;
    if (idx < NV4) {
        src = c1; oh = (__nv_bfloat162*)g_c1h; ol = (__nv_bfloat162*)g_c1l;
    } else {
        k = idx - NV4;
        src = c2; oh = (__nv_bfloat162*)g_c2h; ol = (__nv_bfloat162*)g_c2l;
    }
    float4 v = ((const float4*)src)[k];
    __nv_bfloat16 h0 = __float2bfloat16(v.x), h1 = __float2bfloat16(v.y);
    __nv_bfloat16 h2 = __float2bfloat16(v.z), h3 = __float2bfloat16(v.w);
    oh[k * 2]     = __nv_bfloat162(h0, h1);
    oh[k * 2 + 1] = __nv_bfloat162(h2, h3);
    ol[k * 2]     = __nv_bfloat162(__float2bfloat16(v.x - __bfloat162float(h0)),
                                   __float2bfloat16(v.y - __bfloat162float(h1)));
    ol[k * 2 + 1] = __nv_bfloat162(__float2bfloat16(v.z - __bfloat162float(h2)),
                                   __float2bfloat16(v.w - __bfloat162float(h3)));
}

// ---------------- attention: mma.sync flash, static-offset softmax ----------------
__global__ __launch_bounds__(ATH)
void attn_mma(const unsigned char* __restrict__ cmask, const float* __restrict__ c2)
{
    extern __shared__ char sm[];
    const uint32_t sb = smem_u32(sm);
    const int tid = threadIdx.x;
    const int lane = tid & 31;
    const int w = tid >> 5;
    const int b = blockIdx.y;
    const int q0 = blockIdx.x * BM;

    const int g  = lane >> 2;
    const int t4 = lane & 3;
    const int swz = lane & 7;
    const int r1 = (lane & 7) + 8 * ((lane >> 3) & 1);
    const int r2 = (lane & 7) + 8 * ((lane >> 4) & 1);
    const int s1 = (lane >> 3) & 1;
    const int s2 = (lane >> 4) & 1;

    // stage gate vectors (ga/gb/gc) into smem
    {
        float* gs = (float*)(sm + SG);
        for (int i = tid; i < 256; i += ATH) {
            gs[i] = g_ga[i];
            gs[256 + i] = g_gb[i];
            gs[512 + i] = g_gc[i];
        }
    }

    // ---- Q tile (hi/lo) via cp.async, xor swizzle ----
    {
        const __nv_bfloat16* baseh = g_c2h + ((size_t)b * L_DIM + q0) * D_DIM;
        const __nv_bfloat16* basel = g_c2l + ((size_t)b * L_DIM + q0) * D_DIM;
        #pragma unroll
        for (int it = 0; it < 32; it++) {
            int chunk = it * ATH + tid;
            int buf = chunk >> 12;
            int rem = chunk & 4095;
            int row = rem >> 5, ch = rem & 31;
            const __nv_bfloat16* src = (buf ? basel : baseh) + (size_t)row * D_DIM + ch * 8;
            uint32_t off = (uint32_t)(row * 512 + ((ch ^ (row & 7)) << 4));
            CP16(sb + (buf ? SQL : SQH) + off, src);
        }
        CP_COMMIT();
    }

    const uint32_t aQh = sb + SQH + (uint32_t)(16 * w + r1) * 512;
    const uint32_t aQl = sb + SQL + (uint32_t)(16 * w + r1) * 512;

    float O[32][4];
    #pragma unroll
    for (int n = 0; n < 32; n++)
        #pragma unroll
        for (int q = 0; q < 4; q++) O[n][q] = 0.f;
    float lac0 = 0.f, lac1 = 0.f;

    const unsigned char* mb = cmask + (size_t)b * L_DIM;
    const int rg = q0 + 16 * w + g;
    const int rowblk = (q0 + 16 * w) >> 6;
    const __nv_bfloat16* k1h = g_c1h + (size_t)b * L_DIM * D_DIM;
    const __nv_bfloat16* k1l = g_c1l + (size_t)b * L_DIM * D_DIM;

    #pragma unroll 1
    for (int t = 0; t < NTILE; t++) {
        const int j0 = t * BN;
        __syncthreads();   // all warps done reading previous K tile
        #pragma unroll
        for (int it = 0; it < 16; it++) {
            int chunk = it * ATH + tid;
            int buf = chunk >> 11;
            int rem = chunk & 2047;
            int row = rem >> 5, ch = rem & 31;
            const __nv_bfloat16* src = (buf ? k1l : k1h) + ((size_t)(j0 + row)) * D_DIM + ch * 8;
            uint32_t off = (uint32_t)(row * 512 + ((ch ^ (row & 7)) << 4));
            CP16(sb + (buf ? SKL : SKH) + off, src);
        }
        CP_COMMIT();
        if (tid < 64) {
            int mv = (mb[j0 + tid] != 0);
            unsigned bal = __ballot_sync(0xffffffffu, mv);
            if ((tid & 31) == 0) *(uint32_t*)(sm + SMSK + (tid >> 5) * 4) = bal;
        }
        CP_WAIT(0);
        __syncthreads();

        // ---- QK^T -> S (3-term bf16 split) ----
        float S[8][4];
        #pragma unroll
        for (int n = 0; n < 8; n++)
            #pragma unroll
            for (int q = 0; q < 4; q++) S[n][q] = 0.f;

        #pragma unroll
        for (int kt = 0; kt < 16; kt++) {
            uint32_t qh[4], ql[4];
            uint32_t aoff = (uint32_t)(((2 * kt + s2) ^ swz) << 4);
            ldsm4(aQh + aoff, qh);
            ldsm4(aQl + aoff, ql);
            #pragma unroll
            for (int np = 0; np < 4; np++) {
                uint32_t bh[4], bl[4];
                uint32_t badr = sb + (uint32_t)((16 * np + r2) * 512 + (((2 * kt + s1) ^ swz) << 4));
                ldsm4(badr + SKH, bh);
                ldsm4(badr + SKL, bl);
                mma16816(S[2 * np],     qh, bh);
                mma16816(S[2 * np],     qh, bl);
                mma16816(S[2 * np],     ql, bh);
                mma16816(S[2 * np + 1], qh, bh + 2);
                mma16816(S[2 * np + 1], qh, bl + 2);
                mma16816(S[2 * np + 1], ql, bh + 2);
            }
        }

        // ---- softmax ----
        uint32_t mb0 = *(const uint32_t*)(sm + SMSK);
        uint32_t mb1 = *(const uint32_t*)(sm + SMSK + 4);
        uint64_t mbits = (uint64_t)mb0 | ((uint64_t)mb1 << 32);
        const bool dt = (rowblk == (j0 >> 6));
        const int dg = rg - j0, dg8 = dg + 8;

        uint32_t pg[8], pg8[8], qg[8], qg8[8];
        #pragma unroll
        for (int nt = 0; nt < 8; nt++) {
            int lc = 8 * nt + 2 * t4;
            float p0 = fast_ex2(S[nt][0] * L2E + NEG_C);
            float p1 = fast_ex2(S[nt][1] * L2E + NEG_C);
            float p2 = fast_ex2(S[nt][2] * L2E + NEG_C);
            float p3 = fast_ex2(S[nt][3] * L2E + NEG_C);
            if ((mbits >> lc) & 1)       { p0 = 0.f; p2 = 0.f; }
            if ((mbits >> (lc + 1)) & 1) { p1 = 0.f; p3 = 0.f; }
            if (dt) {
                if (lc == dg)      p0 = 0.f;
                if (lc + 1 == dg)  p1 = 0.f;
                if (lc == dg8)     p2 = 0.f;
                if (lc + 1 == dg8) p3 = 0.f;
            }
            lac0 += p0 + p1;
            lac1 += p2 + p3;
            uint32_t u0 = packbf(p1, p0);
            uint32_t u1 = packbf(p3, p2);
            pg[nt] = u0; pg8[nt] = u1;
            float h0 = __uint_as_float(u0 << 16);
            float h1 = __uint_as_float(u0 & 0xFFFF0000u);
            float h2 = __uint_as_float(u1 << 16);
            float h3 = __uint_as_float(u1 & 0xFFFF0000u);
            qg[nt]  = packbf(p1 - h1, p0 - h0);
            qg8[nt] = packbf(p3 - h3, p2 - h2);
        }

        // ---- O += P @ K ----
        #pragma unroll
        for (int kt = 0; kt < 4; kt++) {
            uint32_t ah[4] = {pg[2 * kt], pg8[2 * kt], pg[2 * kt + 1], pg8[2 * kt + 1]};
            uint32_t al[4] = {qg[2 * kt], qg8[2 * kt], qg[2 * kt + 1], qg8[2 * kt + 1]};
            #pragma unroll
            for (int np = 0; np < 16; np++) {
                uint32_t bh[4], bl[4];
                uint32_t badr = sb + (uint32_t)((16 * kt + r1) * 512 + (((2 * np + s2) ^ swz) << 4));
                ldsm4t(badr + SKH, bh);
                ldsm4t(badr + SKL, bl);
                mma16816(O[2 * np],     ah, bh);
                mma16816(O[2 * np],     ah, bl);
                mma16816(O[2 * np],     al, bh);
                mma16816(O[2 * np + 1], ah, bh + 2);
                mma16816(O[2 * np + 1], ah, bl + 2);
                mma16816(O[2 * np + 1], al, bh + 2);
            }
        }
    }

    // ---- finalize: normalize, compute prod + gate, emit bf16 splits ----
    float l0 = lac0, l1 = lac1;
    l0 += __shfl_xor_sync(0xffffffffu, l0, 1);
    l0 += __shfl_xor_sync(0xffffffffu, l0, 2);
    l1 += __shfl_xor_sync(0xffffffffu, l1, 1);
    l1 += __shfl_xor_sync(0xffffffffu, l1, 2);
    float inv0 = 1.0f / l0, inv1 = 1.0f / l1;

    const size_t r0e = ((size_t)b * L_DIM + rg) * D_DIM;
    const size_t r1e = r0e + 8 * D_DIM;
    const float* c2r0 = c2 + r0e;
    const float* c2r1 = c2 + r1e;
    uint32_t* augh32 = (uint32_t*)g_augh;
    uint32_t* augl32 = (uint32_t*)g_augl;
    uint32_t* prodh32 = (uint32_t*)g_prodh;
    uint32_t* prodl32 = (uint32_t*)g_prodl;
    const float* gs = (const float*)(sm + SG);
    float gate0 = 0.f, gate1 = 0.f;

    #pragma unroll
    for (int nt = 0; nt < 32; nt++) {
        int col = 8 * nt + 2 * t4;
        float a0 = O[nt][0] * inv0, a1 = O[nt][1] * inv0;
        float b0 = O[nt][2] * inv1, b1 = O[nt][3] * inv1;
        float2 x0 = *(const float2*)(c2r0 + col);
        float2 x1 = *(const float2*)(c2r1 + col);
        float p0 = x0.x * a0, p1 = x0.y * a1;
        float p2 = x1.x * b0, p3 = x1.y * b1;
        float ga0 = gs[col], ga1 = gs[col + 1];
        float gb0 = gs[256 + col], gb1 = gs[257 + col];
        float gc0 = gs[512 + col], gc1 = gs[513 + col];
        gate0 += x0.x * ga0 + x0.y * ga1 + a0 * gb0 + a1 * gb1 + p0 * gc0 + p1 * gc1;
        gate1 += x1.x * ga0 + x1.y * ga1 + b0 * gb0 + b1 * gb1 + p2 * gc0 + p3 * gc1;

        uint32_t ah = packbf(a1, a0);
        float ah0 = __uint_as_float(ah << 16), ah1 = __uint_as_float(ah & 0xFFFF0000u);
        uint32_t alw = packbf(a1 - ah1, a0 - ah0);
        uint32_t bh = packbf(b1, b0);
        float bh0 = __uint_as_float(bh << 16), bh1 = __uint_as_float(bh & 0xFFFF0000u);
        uint32_t blw = packbf(b1 - bh1, b0 - bh0);
        uint32_t ph = packbf(p1, p0);
        float ph0 = __uint_as_float(ph << 16), ph1 = __uint_as_float(ph & 0xFFFF0000u);
        uint32_t plw = packbf(p1 - ph1, p0 - ph0);
        uint32_t ph2 = packbf(p3, p2);
        float pc0 = __uint_as_float(ph2 << 16), pc1 = __uint_as_float(ph2 & 0xFFFF0000u);
        uint32_t plw2 = packbf(p3 - pc1, p2 - pc0);

        size_t i0 = (r0e + col) >> 1, i1 = (r1e + col) >> 1;
        augh32[i0] = ah;   augl32[i0] = alw;
        augh32[i1] = bh;   augl32[i1] = blw;
        prodh32[i0] = ph;  prodl32[i0] = plw;
        prodh32[i1] = ph2; prodl32[i1] = plw2;
    }

    gate0 += __shfl_xor_sync(0xffffffffu, gate0, 1);
    gate0 += __shfl_xor_sync(0xffffffffu, gate0, 2);
    gate1 += __shfl_xor_sync(0xffffffffu, gate1, 1);
    gate1 += __shfl_xor_sync(0xffffffffu, gate1, 2);
    if (t4 == 0) {
        g_gate[(size_t)b * L_DIM + rg] = gate0;
        g_gate[(size_t)b * L_DIM + rg + 8] = gate1;
    }
}

// ---------------- fusion on tensor cores, 2-stage cp.async pipeline ----------------
// stage layout: [AH 16K][AL 16K][WH 32K][WL 32K] = 96KB
__device__ __forceinline__ void fus_issue(uint32_t sbase, int kc, size_t row0, int tid)
{
    const int term = kc >> 2;
    const int koff = (kc & 3) * 64;
    const __nv_bfloat16* aH = (term == 0 ? g_c2h : term == 1 ? g_augh : g_prodh) + row0 * D_DIM;
    const __nv_bfloat16* aL = (term == 0 ? g_c2l : term == 1 ? g_augl : g_prodl) + row0 * D_DIM;
    #pragma unroll
    for (int it = 0; it < 8; it++) {
        int c = it * 256 + tid;
        int buf = c >> 10, rem = c & 1023;
        int row = rem >> 3, ch = rem & 7;
        const __nv_bfloat16* src = (buf ? aL : aH) + (size_t)row * D_DIM + koff + ch * 8;
        uint32_t dst = sbase + (buf ? 16384 : 0) + row * 128 + ((ch ^ (row & 7)) << 4);
        CP16(dst, src);
    }
    const int krow0 = term * 256 + koff;
    #pragma unroll
    for (int it = 0; it < 16; it++) {
        int c = it * 256 + tid;
        int buf = c >> 11, rem = c & 2047;
        int row = rem >> 5, ch = rem & 31;
        const __nv_bfloat16* src = (buf ? g_Wcl : g_Wch) + (size_t)(krow0 + row) * D_DIM + ch * 8;
        uint32_t dst = sbase + (buf ? 65536 : 32768) + row * 512 + ((ch ^ (row & 7)) << 4);
        CP16(dst, src);
    }
}

__global__ __launch_bounds__(256)
void fusion_tc(const float* __restrict__ c2, const float* __restrict__ bf,
               const float* __restrict__ bg, float* __restrict__ out)
{
    extern __shared__ char sm[];
    const uint32_t sb = smem_u32(sm);
    const int tid = threadIdx.x;
    const int lane = tid & 31;
    const int w = tid >> 5;
    const int g = lane >> 2;
    const int t4 = lane & 3;
    const int swz = lane & 7;
    const int r1 = (lane & 7) + 8 * ((lane >> 3) & 1);
    const int s2 = (lane >> 4) & 1;
    const size_t row0 = (size_t)blockIdx.x * 128;

    ((float*)(sm + FS_BF))[tid] = bf[tid];

    float O[32][4];
    #pragma unroll
    for (int n = 0; n < 32; n++)
        #pragma unroll
        for (int q = 0; q < 4; q++) O[n][q] = 0.f;

    fus_issue(sb, 0, row0, tid);         CP_COMMIT();
    fus_issue(sb + FSTG, 1, row0, tid);  CP_COMMIT();

    #pragma unroll 1
    for (int kc = 0; kc < 12; kc++) {
        if (kc == 11) { CP_WAIT(0); } else { CP_WAIT(1); }
        __syncthreads();

        const uint32_t sbase = sb + (kc & 1) * FSTG;
        const uint32_t aAh = sbase + (uint32_t)(16 * w + r1) * 128;
        const uint32_t aAl = sbase + 16384 + (uint32_t)(16 * w + r1) * 128;
        #pragma unroll
        for (int kt = 0; kt < 4; kt++) {
            uint32_t ah[4], al[4];
            uint32_t aoff = (uint32_t)(((2 * kt + s2) ^ swz) << 4);
            ldsm4(aAh + aoff, ah);
            ldsm4(aAl + aoff, al);
            #pragma unroll
            for (int np = 0; np < 16; np++) {
                uint32_t bh[4], bl[4];
                uint32_t badr = sbase + (uint32_t)((16 * kt + r1) * 512 + (((2 * np + s2) ^ swz) << 4));
                ldsm4t(badr + 32768, bh);
                ldsm4t(badr + 65536, bl);
                mma16816(O[2 * np],     ah, bh);
                mma16816(O[2 * np],     ah, bl);
                mma16816(O[2 * np],     al, bh);
                mma16816(O[2 * np + 1], ah, bh + 2);
                mma16816(O[2 * np + 1], ah, bl + 2);
                mma16816(O[2 * np + 1], al, bh + 2);
            }
        }
        __syncthreads();
        if (kc < 10) {
            fus_issue(sb + (kc & 1) * FSTG, kc + 2, row0, tid);
            CP_COMMIT();
        }
    }

    // epilogue
    const size_t rg = row0 + 16 * w + g;
    const float bgv = bg[0];
    float gv0 = 1.0f / (1.0f + __expf(-(g_gate[rg] + bgv)));
    float gv1 = 1.0f / (1.0f + __expf(-(g_gate[rg + 8] + bgv)));
    const float* c2r0 = c2 + rg * D_DIM;
    const float* c2r1 = c2r0 + 8 * D_DIM;
    float* o0 = out + rg * D_DIM;
    float* o1 = o0 + 8 * D_DIM;
    const float* bfs = (const float*)(sm + FS_BF);

    #pragma unroll
    for (int nt = 0; nt < 32; nt++) {
        int col = 8 * nt + 2 * t4;
        float2 bv = *(const float2*)(bfs + col);
        float2 x0 = *(const float2*)(c2r0 + col);
        float2 x1 = *(const float2*)(c2r1 + col);
        float f0 = tanhf(O[nt][0] + bv.x);
        float f1 = tanhf(O[nt][1] + bv.y);
        float f2 = tanhf(O[nt][2] + bv.x);
        float f3 = tanhf(O[nt][3] + bv.y);
        *(float2*)(o0 + col) = make_float2(gv0 * f0 + (1.f - gv0) * x0.x,
                                           gv0 * f1 + (1.f - gv0) * x0.y);
        *(float2*)(o1 + col) = make_float2(gv1 * f2 + (1.f - gv1) * x1.x,
                                           gv1 * f3 + (1.f - gv1) * x1.y);
    }
}

extern "C" void kernel_launch(void* const* d_in, const int* in_sizes, int n_in,
                              void* d_out, int out_size)
{
    (void)in_sizes; (void)n_in; (void)out_size;
    const float* c1         = (const float*)d_in[0];
    const float* c2         = (const float*)d_in[1];
    const unsigned char* cm = (const unsigned char*)d_in[2];
    const float* Wf         = (const float*)d_in[3];
    const float* bf         = (const float*)d_in[4];
    const float* Wg         = (const float*)d_in[5];
    const float* bg         = (const float*)d_in[6];
    float* out              = (float*)d_out;

    prep_kernel<<<256, 256>>>(Wf, Wg);
    convert_hl<<<2 * NV4 / 256, 256>>>(c1, c2);

    cudaFuncSetAttribute(attn_mma, cudaFuncAttributeMaxDynamicSharedMemorySize, ATT_SMEM);
    attn_mma<<<dim3(L_DIM / BM, B_DIM), ATH, ATT_SMEM>>>(cm, c2);

    cudaFuncSetAttribute(fusion_tc, cudaFuncAttributeMaxDynamicSharedMemorySize, FUS_SMEM);
    fusion_tc<<<NROW / 128, 256, FUS_SMEM>>>(c2, bf, bg, out);
}

// round 9
// speedup vs baseline: 3.5649x; 1.0069x over previous
#include <cuda_runtime.h>
#include <cuda_bf16.h>
#include <cstdint>
#include <math.h>

#define B_DIM 8
#define L_DIM 2048
#define D_DIM 256
#define NROW (B_DIM * L_DIM)

// attention tiling
#define BM 128
#define BN 64
#define NTILE (L_DIM / BN)   // 32
#define ATH 256
#define L2E 1.44269504f
#define NEG_C (-57.7078016f) // -40 * log2(e)

// smem byte offsets
#define SQH 0
#define SQL 65536
#define SKH 131072
#define SKL 163840
#define FST0 0
#define FST1 98304
#define SMSK 196608
#define SG   196624
#define SBF  199696
#define ATT_SMEM 200768

// ---------------- device scratch ----------------
__device__ float g_ga[D_DIM];
__device__ float g_gb[D_DIM];
__device__ float g_gc[D_DIM];
__device__ __nv_bfloat16 g_Wch[3 * D_DIM * D_DIM];   // [768][256] folded weights hi
__device__ __nv_bfloat16 g_Wcl[3 * D_DIM * D_DIM];   // lo
__device__ __nv_bfloat16 g_c1h[(size_t)NROW * D_DIM];
__device__ __nv_bfloat16 g_c1l[(size_t)NROW * D_DIM];
__device__ __nv_bfloat16 g_augh[(size_t)NROW * D_DIM];
__device__ __nv_bfloat16 g_augl[(size_t)NROW * D_DIM];
__device__ __nv_bfloat16 g_prodh[(size_t)NROW * D_DIM];
__device__ __nv_bfloat16 g_prodl[(size_t)NROW * D_DIM];

// ---------------- helpers ----------------
__device__ __forceinline__ uint32_t smem_u32(const void* p) {
    uint32_t a;
    asm("{ .reg .u64 t; cvta.to.shared.u64 t, %1; cvt.u32.u64 %0, t; }" : "=r"(a) : "l"(p));
    return a;
}
#define CP16(dst, src) asm volatile("cp.async.cg.shared.global [%0], [%1], 16;" :: "r"(dst), "l"(src))
#define CP_COMMIT()    asm volatile("cp.async.commit_group;" ::: "memory")
#define CP_WAIT(n)     asm volatile("cp.async.wait_group %0;" :: "n"(n) : "memory")

__device__ __forceinline__ void ldsm4(uint32_t addr, uint32_t r[4]) {
    asm volatile("ldmatrix.sync.aligned.m8n8.x4.shared.b16 {%0,%1,%2,%3}, [%4];"
        : "=r"(r[0]), "=r"(r[1]), "=r"(r[2]), "=r"(r[3]) : "r"(addr));
}
__device__ __forceinline__ void ldsm4t(uint32_t addr, uint32_t r[4]) {
    asm volatile("ldmatrix.sync.aligned.m8n8.x4.trans.shared.b16 {%0,%1,%2,%3}, [%4];"
        : "=r"(r[0]), "=r"(r[1]), "=r"(r[2]), "=r"(r[3]) : "r"(addr));
}
__device__ __forceinline__ void mma16816(float d[4], const uint32_t a[4], const uint32_t b[2]) {
    asm volatile(
        "mma.sync.aligned.m16n8k16.row.col.f32.bf16.bf16.f32 "
        "{%0,%1,%2,%3}, {%4,%5,%6,%7}, {%8,%9}, {%0,%1,%2,%3};"
        : "+f"(d[0]), "+f"(d[1]), "+f"(d[2]), "+f"(d[3])
        : "r"(a[0]), "r"(a[1]), "r"(a[2]), "r"(a[3]), "r"(b[0]), "r"(b[1]));
}
__device__ __forceinline__ float fast_ex2(float x) {
    float r;
    asm("ex2.approx.f32 %0, %1;" : "=f"(r) : "f"(x));
    return r;
}
__device__ __forceinline__ uint32_t packbf(float hi, float lo) {
    uint32_t d;
    asm("cvt.rn.bf16x2.f32 %0, %1, %2;" : "=r"(d) : "f"(hi), "f"(lo));
    return d;
}

// ---------------- prep: fold fusion weights, split to bf16 ----------------
__global__ void prep_kernel(const float* __restrict__ Wf, const float* __restrict__ Wg)
{
    int i = blockIdx.x * blockDim.x + threadIdx.x;
    if (i < D_DIM * D_DIM) {
        int k = i >> 8, d = i & 255;
        float w4 = Wf[(size_t)(768 + k) * D_DIM + d];
        float wa = Wf[(size_t)k * D_DIM + d] + w4;
        float wb = Wf[(size_t)(256 + k) * D_DIM + d] - w4;
        float wc = Wf[(size_t)(512 + k) * D_DIM + d];
        float w3[3] = {wa, wb, wc};
        #pragma unroll
        for (int tmc = 0; tmc < 3; tmc++) {
            __nv_bfloat16 h = __float2bfloat16(w3[tmc]);
            size_t o = (size_t)(tmc * D_DIM + k) * D_DIM + d;
            g_Wch[o] = h;
            g_Wcl[o] = __float2bfloat16(w3[tmc] - __bfloat162float(h));
        }
    }
    if (i < D_DIM) {
        float v4 = Wg[768 + i];
        g_ga[i] = Wg[i] + v4;
        g_gb[i] = Wg[256 + i] - v4;
        g_gc[i] = Wg[512 + i];
    }
}

// ---------------- convert c1 -> bf16 hi/lo ----------------
__global__ void convert_c1k(const float* __restrict__ c1)
{
    int k = blockIdx.x * blockDim.x + threadIdx.x;
    float4 v = ((const float4*)c1)[k];
    __nv_bfloat162* oh = (__nv_bfloat162*)g_c1h;
    __nv_bfloat162* ol = (__nv_bfloat162*)g_c1l;
    __nv_bfloat16 h0 = __float2bfloat16(v.x), h1 = __float2bfloat16(v.y);
    __nv_bfloat16 h2 = __float2bfloat16(v.z), h3 = __float2bfloat16(v.w);
    oh[k * 2]     = __nv_bfloat162(h0, h1);
    oh[k * 2 + 1] = __nv_bfloat162(h2, h3);
    ol[k * 2]     = __nv_bfloat162(__float2bfloat16(v.x - __bfloat162float(h0)),
                                   __float2bfloat16(v.y - __bfloat162float(h1)));
    ol[k * 2 + 1] = __nv_bfloat162(__float2bfloat16(v.z - __bfloat162float(h2)),
                                   __float2bfloat16(v.w - __bfloat162float(h3)));
}

// ---------------- fusion stage loaders ----------------
// terms 1/2 (aug, prod): A 128x64 h/l + W 64x256 h/l into a 96KB stage
__device__ __forceinline__ void fus_issue12(uint32_t stage, int c, size_t row0, int tid)
{
    int cm = c - 4;
    int term = cm >> 2;                 // 0 -> aug, 1 -> prod
    int koff = (cm & 3) * 64;
    const __nv_bfloat16* aH = (term == 0 ? g_augh : g_prodh) + row0 * D_DIM;
    const __nv_bfloat16* aL = (term == 0 ? g_augl : g_prodl) + row0 * D_DIM;
    #pragma unroll
    for (int it = 0; it < 8; it++) {
        int cth = it * 256 + tid;
        int buf = cth >> 10, rem = cth & 1023;
        int row = rem >> 3, ch = rem & 7;
        const __nv_bfloat16* src = (buf ? aL : aH) + (size_t)row * D_DIM + koff + ch * 8;
        CP16(stage + (buf ? 16384 : 0) + row * 128 + ((ch ^ (row & 7)) << 4), src);
    }
    int krow0 = (term + 1) * 256 + koff;
    #pragma unroll
    for (int it = 0; it < 16; it++) {
        int cth = it * 256 + tid;
        int buf = cth >> 11, rem = cth & 2047;
        int row = rem >> 5, ch = rem & 31;
        const __nv_bfloat16* src = (buf ? g_Wcl : g_Wch) + (size_t)(krow0 + row) * D_DIM + ch * 8;
        CP16(stage + (buf ? 65536 : 32768) + row * 512 + ((ch ^ (row & 7)) << 4), src);
    }
}

// term 0 (c2): W only, into K region
__device__ __forceinline__ void fus_issueW0(uint32_t sb, int t, int tid)
{
    int krow0 = t * 64;
    #pragma unroll
    for (int it = 0; it < 16; it++) {
        int cth = it * 256 + tid;
        int buf = cth >> 11, rem = cth & 2047;
        int row = rem >> 5, ch = rem & 31;
        const __nv_bfloat16* src = (buf ? g_Wcl : g_Wch) + (size_t)(krow0 + row) * D_DIM + ch * 8;
        CP16(sb + (buf ? SKL : SKH) + row * 512 + ((ch ^ (row & 7)) << 4), src);
    }
}

// ---------------- fused attention + fusion kernel ----------------
__global__ __launch_bounds__(ATH)
void fused_kernel(const unsigned char* __restrict__ cmask, const float* __restrict__ c2,
                  const float* __restrict__ bf, const float* __restrict__ bg,
                  float* __restrict__ out)
{
    extern __shared__ char sm[];
    const uint32_t sb = smem_u32(sm);
    const int tid = threadIdx.x;
    const int lane = tid & 31;
    const int w = tid >> 5;
    const int b = blockIdx.y;
    const int q0 = blockIdx.x * BM;

    const int g  = lane >> 2;
    const int t4 = lane & 3;
    const int swz = lane & 7;
    const int r1 = (lane & 7) + 8 * ((lane >> 3) & 1);
    const int r2 = (lane & 7) + 8 * ((lane >> 4) & 1);
    const int s1 = (lane >> 3) & 1;
    const int s2 = (lane >> 4) & 1;

    // ---- preamble: gates + bf to smem; c2 fp32 -> Q hi/lo smem (inline split) ----
    {
        float* gs = (float*)(sm + SG);
        for (int i = tid; i < 256; i += ATH) {
            gs[i] = g_ga[i];
            gs[256 + i] = g_gb[i];
            gs[512 + i] = g_gc[i];
        }
        ((float*)(sm + SBF))[tid] = bf[tid];

        const float* c2b = c2 + ((size_t)b * L_DIM + q0) * D_DIM;
        #pragma unroll 4
        for (int it = 0; it < 32; it++) {
            int f = it * 256 + tid;           // float4 index 0..8191
            int row = f >> 6, fc = f & 63;
            float4 v = *(const float4*)(c2b + (size_t)row * D_DIM + fc * 4);
            uint32_t h01 = packbf(v.y, v.x);
            uint32_t h23 = packbf(v.w, v.z);
            float hx = __uint_as_float(h01 << 16);
            float hy = __uint_as_float(h01 & 0xFFFF0000u);
            float hz = __uint_as_float(h23 << 16);
            float hw = __uint_as_float(h23 & 0xFFFF0000u);
            uint32_t l01 = packbf(v.y - hy, v.x - hx);
            uint32_t l23 = packbf(v.w - hw, v.z - hz);
            int ch = fc >> 1, half = fc & 1;
            uint32_t off = (uint32_t)(row * 512 + ((ch ^ (row & 7)) << 4) + half * 8);
            *(uint2*)(sm + SQH + off) = make_uint2(h01, h23);
            *(uint2*)(sm + SQL + off) = make_uint2(l01, l23);
        }
    }

    const uint32_t aQh = sb + SQH + (uint32_t)(16 * w + r1) * 512;
    const uint32_t aQl = sb + SQL + (uint32_t)(16 * w + r1) * 512;

    float O[32][4];
    #pragma unroll
    for (int n = 0; n < 32; n++)
        #pragma unroll
        for (int q = 0; q < 4; q++) O[n][q] = 0.f;
    float lac0 = 0.f, lac1 = 0.f;

    const unsigned char* mb = cmask + (size_t)b * L_DIM;
    const int rg = q0 + 16 * w + g;
    const int rowblk = (q0 + 16 * w) >> 6;
    const __nv_bfloat16* k1h = g_c1h + (size_t)b * L_DIM * D_DIM;
    const __nv_bfloat16* k1l = g_c1l + (size_t)b * L_DIM * D_DIM;

    // ================= attention mainloop =================
    #pragma unroll 1
    for (int t = 0; t < NTILE; t++) {
        const int j0 = t * BN;
        __syncthreads();
        #pragma unroll
        for (int it = 0; it < 16; it++) {
            int chunk = it * ATH + tid;
            int buf = chunk >> 11;
            int rem = chunk & 2047;
            int row = rem >> 5, ch = rem & 31;
            const __nv_bfloat16* src = (buf ? k1l : k1h) + ((size_t)(j0 + row)) * D_DIM + ch * 8;
            uint32_t off = (uint32_t)(row * 512 + ((ch ^ (row & 7)) << 4));
            CP16(sb + (buf ? SKL : SKH) + off, src);
        }
        CP_COMMIT();
        if (tid < 64) {
            int mv = (mb[j0 + tid] != 0);
            unsigned bal = __ballot_sync(0xffffffffu, mv);
            if ((tid & 31) == 0) *(uint32_t*)(sm + SMSK + (tid >> 5) * 4) = bal;
        }
        CP_WAIT(0);
        __syncthreads();

        // QK^T -> S (3-term bf16 split)
        float S[8][4];
        #pragma unroll
        for (int n = 0; n < 8; n++)
            #pragma unroll
            for (int q = 0; q < 4; q++) S[n][q] = 0.f;

        #pragma unroll
        for (int kt = 0; kt < 16; kt++) {
            uint32_t qh[4], ql[4];
            uint32_t aoff = (uint32_t)(((2 * kt + s2) ^ swz) << 4);
            ldsm4(aQh + aoff, qh);
            ldsm4(aQl + aoff, ql);
            #pragma unroll
            for (int np = 0; np < 4; np++) {
                uint32_t bh[4], bl[4];
                uint32_t badr = sb + (uint32_t)((16 * np + r2) * 512 + (((2 * kt + s1) ^ swz) << 4));
                ldsm4(badr + SKH, bh);
                ldsm4(badr + SKL, bl);
                mma16816(S[2 * np],     qh, bh);
                mma16816(S[2 * np],     qh, bl);
                mma16816(S[2 * np],     ql, bh);
                mma16816(S[2 * np + 1], qh, bh + 2);
                mma16816(S[2 * np + 1], qh, bl + 2);
                mma16816(S[2 * np + 1], ql, bh + 2);
            }
        }

        // softmax (static offset)
        uint32_t mb0 = *(const uint32_t*)(sm + SMSK);
        uint32_t mb1 = *(const uint32_t*)(sm + SMSK + 4);
        uint64_t mbits = (uint64_t)mb0 | ((uint64_t)mb1 << 32);
        const bool dt = (rowblk == (j0 >> 6));
        const int dg = rg - j0, dg8 = dg + 8;

        uint32_t pg[8], pg8[8], qg[8], qg8[8];
        #pragma unroll
        for (int nt = 0; nt < 8; nt++) {
            int lc = 8 * nt + 2 * t4;
            float p0 = fast_ex2(S[nt][0] * L2E + NEG_C);
            float p1 = fast_ex2(S[nt][1] * L2E + NEG_C);
            float p2 = fast_ex2(S[nt][2] * L2E + NEG_C);
            float p3 = fast_ex2(S[nt][3] * L2E + NEG_C);
            if ((mbits >> lc) & 1)       { p0 = 0.f; p2 = 0.f; }
            if ((mbits >> (lc + 1)) & 1) { p1 = 0.f; p3 = 0.f; }
            if (dt) {
                if (lc == dg)      p0 = 0.f;
                if (lc + 1 == dg)  p1 = 0.f;
                if (lc == dg8)     p2 = 0.f;
                if (lc + 1 == dg8) p3 = 0.f;
            }
            lac0 += p0 + p1;
            lac1 += p2 + p3;
            uint32_t u0 = packbf(p1, p0);
            uint32_t u1 = packbf(p3, p2);
            pg[nt] = u0; pg8[nt] = u1;
            float h0 = __uint_as_float(u0 << 16);
            float h1 = __uint_as_float(u0 & 0xFFFF0000u);
            float h2 = __uint_as_float(u1 << 16);
            float h3 = __uint_as_float(u1 & 0xFFFF0000u);
            qg[nt]  = packbf(p1 - h1, p0 - h0);
            qg8[nt] = packbf(p3 - h3, p2 - h2);
        }

        // O += P @ K
        #pragma unroll
        for (int kt = 0; kt < 4; kt++) {
            uint32_t ah[4] = {pg[2 * kt], pg8[2 * kt], pg[2 * kt + 1], pg8[2 * kt + 1]};
            uint32_t al[4] = {qg[2 * kt], qg8[2 * kt], qg[2 * kt + 1], qg8[2 * kt + 1]};
            #pragma unroll
            for (int np = 0; np < 16; np++) {
                uint32_t bh[4], bl[4];
                uint32_t badr = sb + (uint32_t)((16 * kt + r1) * 512 + (((2 * np + s2) ^ swz) << 4));
                ldsm4t(badr + SKH, bh);
                ldsm4t(badr + SKL, bl);
                mma16816(O[2 * np],     ah, bh);
                mma16816(O[2 * np],     ah, bl);
                mma16816(O[2 * np],     al, bh);
                mma16816(O[2 * np + 1], ah, bh + 2);
                mma16816(O[2 * np + 1], ah, bl + 2);
                mma16816(O[2 * np + 1], al, bh + 2);
            }
        }
    }

    // ================= attention epilogue =================
    __syncthreads();                       // all warps done with K region
    fus_issueW0(sb, 0, tid);               // prefetch fusion term0 W chunk 0
    CP_COMMIT();

    float l0 = lac0, l1 = lac1;
    l0 += __shfl_xor_sync(0xffffffffu, l0, 1);
    l0 += __shfl_xor_sync(0xffffffffu, l0, 2);
    l1 += __shfl_xor_sync(0xffffffffu, l1, 1);
    l1 += __shfl_xor_sync(0xffffffffu, l1, 2);
    float inv0 = 1.0f / l0, inv1 = 1.0f / l1;

    const size_t row0 = (size_t)b * L_DIM + q0;
    const size_t r0e = ((size_t)b * L_DIM + rg) * D_DIM;
    const size_t r1e = r0e + 8 * D_DIM;
    const float* c2r0 = c2 + r0e;
    const float* c2r1 = c2 + r1e;
    uint32_t* augh32 = (uint32_t*)g_augh;
    uint32_t* augl32 = (uint32_t*)g_augl;
    uint32_t* prodh32 = (uint32_t*)g_prodh;
    uint32_t* prodl32 = (uint32_t*)g_prodl;
    const float* gs = (const float*)(sm + SG);
    float gate0 = 0.f, gate1 = 0.f;

    #pragma unroll
    for (int nt = 0; nt < 32; nt++) {
        int col = 8 * nt + 2 * t4;
        float a0 = O[nt][0] * inv0, a1 = O[nt][1] * inv0;
        float b0 = O[nt][2] * inv1, b1 = O[nt][3] * inv1;
        float2 x0 = *(const float2*)(c2r0 + col);
        float2 x1 = *(const float2*)(c2r1 + col);
        float p0 = x0.x * a0, p1 = x0.y * a1;
        float p2 = x1.x * b0, p3 = x1.y * b1;
        float ga0 = gs[col], ga1 = gs[col + 1];
        float gb0 = gs[256 + col], gb1 = gs[257 + col];
        float gc0 = gs[512 + col], gc1 = gs[513 + col];
        gate0 += x0.x * ga0 + x0.y * ga1 + a0 * gb0 + a1 * gb1 + p0 * gc0 + p1 * gc1;
        gate1 += x1.x * ga0 + x1.y * ga1 + b0 * gb0 + b1 * gb1 + p2 * gc0 + p3 * gc1;

        uint32_t ah = packbf(a1, a0);
        float ah0 = __uint_as_float(ah << 16), ah1 = __uint_as_float(ah & 0xFFFF0000u);
        uint32_t alw = packbf(a1 - ah1, a0 - ah0);
        uint32_t bh = packbf(b1, b0);
        float bh0 = __uint_as_float(bh << 16), bh1 = __uint_as_float(bh & 0xFFFF0000u);
        uint32_t blw = packbf(b1 - bh1, b0 - bh0);
        uint32_t ph = packbf(p1, p0);
        float ph0 = __uint_as_float(ph << 16), ph1 = __uint_as_float(ph & 0xFFFF0000u);
        uint32_t plw = packbf(p1 - ph1, p0 - ph0);
        uint32_t ph2 = packbf(p3, p2);
        float pc0 = __uint_as_float(ph2 << 16), pc1 = __uint_as_float(ph2 & 0xFFFF0000u);
        uint32_t plw2 = packbf(p3 - pc1, p2 - pc0);

        size_t i0 = (r0e + col) >> 1, i1 = (r1e + col) >> 1;
        augh32[i0] = ah;   augl32[i0] = alw;
        augh32[i1] = bh;   augl32[i1] = blw;
        prodh32[i0] = ph;  prodl32[i0] = plw;
        prodh32[i1] = ph2; prodl32[i1] = plw2;
    }

    gate0 += __shfl_xor_sync(0xffffffffu, gate0, 1);
    gate0 += __shfl_xor_sync(0xffffffffu, gate0, 2);
    gate1 += __shfl_xor_sync(0xffffffffu, gate1, 1);
    gate1 += __shfl_xor_sync(0xffffffffu, gate1, 2);

    // ================= fusion GEMM tail =================
    float F[32][4];
    #pragma unroll
    for (int n = 0; n < 32; n++)
        #pragma unroll
        for (int q = 0; q < 4; q++) F[n][q] = 0.f;

    // term 0: A = c2 (Q smem), W staged in K region, single-buffered
    #pragma unroll 1
    for (int t = 0; t < 4; t++) {
        CP_WAIT(0);
        __syncthreads();
        #pragma unroll
        for (int kt = 0; kt < 4; kt++) {
            uint32_t ah[4], al[4];
            uint32_t aoff = (uint32_t)(((2 * (4 * t + kt) + s2) ^ swz) << 4);
            ldsm4(aQh + aoff, ah);
            ldsm4(aQl + aoff, al);
            #pragma unroll
            for (int np = 0; np < 16; np++) {
                uint32_t bh[4], bl[4];
                uint32_t badr = sb + (uint32_t)((16 * kt + r1) * 512 + (((2 * np + s2) ^ swz) << 4));
                ldsm4t(badr + SKH, bh);
                ldsm4t(badr + SKL, bl);
                mma16816(F[2 * np],     ah, bh);
                mma16816(F[2 * np],     ah, bl);
                mma16816(F[2 * np],     al, bh);
                mma16816(F[2 * np + 1], ah, bh + 2);
                mma16816(F[2 * np + 1], ah, bl + 2);
                mma16816(F[2 * np + 1], al, bh + 2);
            }
        }
        __syncthreads();
        if (t < 3) { fus_issueW0(sb, t + 1, tid); CP_COMMIT(); }
    }

    // terms 1/2: A = aug/prod (global via L2), 2-stage pipeline in freed Q+K smem
    fus_issue12(sb + FST0, 4, row0, tid); CP_COMMIT();
    fus_issue12(sb + FST1, 5, row0, tid); CP_COMMIT();

    #pragma unroll 1
    for (int c = 4; c < 12; c++) {
        if (c == 11) { CP_WAIT(0); } else { CP_WAIT(1); }
        __syncthreads();
        const uint32_t stage = sb + ((c & 1) ? FST1 : FST0);
        const uint32_t aAh = stage + (uint32_t)(16 * w + r1) * 128;
        const uint32_t aAl = stage + 16384 + (uint32_t)(16 * w + r1) * 128;
        #pragma unroll
        for (int kt = 0; kt < 4; kt++) {
            uint32_t ah[4], al[4];
            uint32_t aoff = (uint32_t)(((2 * kt + s2) ^ swz) << 4);
            ldsm4(aAh + aoff, ah);
            ldsm4(aAl + aoff, al);
            #pragma unroll
            for (int np = 0; np < 16; np++) {
                uint32_t bh[4], bl[4];
                uint32_t badr = stage + (uint32_t)((16 * kt + r1) * 512 + (((2 * np + s2) ^ swz) << 4));
                ldsm4t(badr + 32768, bh);
                ldsm4t(badr + 65536, bl);
                mma16816(F[2 * np],     ah, bh);
                mma16816(F[2 * np],     ah, bl);
                mma16816(F[2 * np],     al, bh);
                mma16816(F[2 * np + 1], ah, bh + 2);
                mma16816(F[2 * np + 1], ah, bl + 2);
                mma16816(F[2 * np + 1], al, bh + 2);
            }
        }
        __syncthreads();
        if (c < 10) {
            fus_issue12(sb + ((c & 1) ? FST1 : FST0), c + 2, row0, tid);
            CP_COMMIT();
        }
    }

    // ---- output epilogue ----
    const float bgv = bg[0];
    float gv0 = 1.0f / (1.0f + __expf(-(gate0 + bgv)));
    float gv1 = 1.0f / (1.0f + __expf(-(gate1 + bgv)));
    float* o0 = out + r0e;
    float* o1 = out + r1e;
    const float* bfs = (const float*)(sm + SBF);

    #pragma unroll
    for (int nt = 0; nt < 32; nt++) {
        int col = 8 * nt + 2 * t4;
        float2 bv = *(const float2*)(bfs + col);
        float2 x0 = *(const float2*)(c2r0 + col);
        float2 x1 = *(const float2*)(c2r1 + col);
        float f0 = tanhf(F[nt][0] + bv.x);
        float f1 = tanhf(F[nt][1] + bv.y);
        float f2 = tanhf(F[nt][2] + bv.x);
        float f3 = tanhf(F[nt][3] + bv.y);
        *(float2*)(o0 + col) = make_float2(gv0 * f0 + (1.f - gv0) * x0.x,
                                           gv0 * f1 + (1.f - gv0) * x0.y);
        *(float2*)(o1 + col) = make_float2(gv1 * f2 + (1.f - gv1) * x1.x,
                                           gv1 * f3 + (1.f - gv1) * x1.y);
    }
}

extern "C" void kernel_launch(void* const* d_in, const int* in_sizes, int n_in,
                              void* d_out, int out_size)
{
    (void)in_sizes; (void)n_in; (void)out_size;
    const float* c1         = (const float*)d_in[0];
    const float* c2         = (const float*)d_in[1];
    const unsigned char* cm = (const unsigned char*)d_in[2];
    const float* Wf         = (const float*)d_in[3];
    const float* bf         = (const float*)d_in[4];
    const float* Wg         = (const float*)d_in[5];
    const float* bg         = (const float*)d_in[6];
    float* out              = (float*)d_out;

    prep_kernel<<<256, 256>>>(Wf, Wg);
    convert_c1k<<<NROW * D_DIM / 4 / 256, 256>>>(c1);

    cudaFuncSetAttribute(fused_kernel, cudaFuncAttributeMaxDynamicSharedMemorySize, ATT_SMEM);
    fused_kernel<<<dim3(L_DIM / BM, B_DIM), ATH, ATT_SMEM>>>(cm, c2, bf, bg, out);
}